// round 10
// baseline (speedup 1.0000x reference)
#include <cuda_runtime.h>
#include <cuda_bf16.h>
#include <cstdint>

// Problem constants
#define BATCH   4
#define SEQ     2048
#define DMODEL  1024
#define HEADS   16
#define DHEAD   64
#define EDIM    1024
#define MROWS   (BATCH * SEQ)     // 8192
#define K3      3072              // split-bf16 K' = 3*1024

// ---------------------------------------------------------------------------
// Scratch (device globals; no allocation allowed)
// ---------------------------------------------------------------------------
__device__ __align__(256) __nv_bfloat16 g_Qh[(size_t)BATCH * HEADS * SEQ * DHEAD];
__device__ __align__(256) __nv_bfloat16 g_Ql[(size_t)BATCH * HEADS * SEQ * DHEAD];
__device__ __align__(256) __nv_bfloat16 g_Kh[(size_t)BATCH * HEADS * SEQ * DHEAD];
__device__ __align__(256) __nv_bfloat16 g_Kl[(size_t)BATCH * HEADS * SEQ * DHEAD];
__device__ __align__(256) __nv_bfloat16 g_Vh[(size_t)BATCH * HEADS * SEQ * DHEAD];
__device__ __align__(256) __nv_bfloat16 g_Vl[(size_t)BATCH * HEADS * SEQ * DHEAD];
__device__ __align__(256) __nv_bfloat16 g_Aq [(size_t)MROWS * K3];
__device__ __align__(256) __nv_bfloat16 g_Akv[(size_t)MROWS * K3];
__device__ __align__(256) __nv_bfloat16 g_Oc [(size_t)MROWS * K3];
__device__ __align__(256) __nv_bfloat16 g_Wqc [(size_t)1024 * K3];
__device__ __align__(256) __nv_bfloat16 g_Wkvc[(size_t)2048 * K3];
__device__ __align__(256) __nv_bfloat16 g_W0c [(size_t)1024 * K3];

// ---------------------------------------------------------------------------
// Helpers
// ---------------------------------------------------------------------------
__device__ __forceinline__ uint32_t smem_u32(const void* p) {
    uint32_t a;
    asm("{ .reg .u64 t; cvta.to.shared.u64 t, %1; cvt.u32.u64 %0, t; }" : "=r"(a) : "l"(p));
    return a;
}
__device__ __forceinline__ void cp_async16(uint32_t smem_addr, const void* gptr) {
    asm volatile("cp.async.cg.shared.global [%0], [%1], 16;" :: "r"(smem_addr), "l"(gptr));
}
#define CP_COMMIT() asm volatile("cp.async.commit_group;" ::: "memory")
#define CP_WAIT(n)  asm volatile("cp.async.wait_group %0;" :: "n"(n) : "memory")

__device__ __forceinline__ void ldmatrix_x4(uint32_t& r0, uint32_t& r1, uint32_t& r2,
                                            uint32_t& r3, uint32_t addr) {
    asm volatile("ldmatrix.sync.aligned.m8n8.x4.shared.b16 {%0,%1,%2,%3}, [%4];"
                 : "=r"(r0), "=r"(r1), "=r"(r2), "=r"(r3) : "r"(addr));
}
__device__ __forceinline__ void ldmatrix_x4_trans(uint32_t& r0, uint32_t& r1, uint32_t& r2,
                                                  uint32_t& r3, uint32_t addr) {
    asm volatile("ldmatrix.sync.aligned.m8n8.x4.trans.shared.b16 {%0,%1,%2,%3}, [%4];"
                 : "=r"(r0), "=r"(r1), "=r"(r2), "=r"(r3) : "r"(addr));
}
__device__ __forceinline__ void mma_bf16(float* c,
                                         uint32_t a0, uint32_t a1, uint32_t a2, uint32_t a3,
                                         uint32_t b0, uint32_t b1) {
    asm volatile(
        "mma.sync.aligned.m16n8k16.row.col.f32.bf16.bf16.f32 "
        "{%0,%1,%2,%3}, {%4,%5,%6,%7}, {%8,%9}, {%0,%1,%2,%3};"
        : "+f"(c[0]), "+f"(c[1]), "+f"(c[2]), "+f"(c[3])
        : "r"(a0), "r"(a1), "r"(a2), "r"(a3), "r"(b0), "r"(b1));
}
__device__ __forceinline__ uint32_t pack_bf16x2(float x, float y) {
    __nv_bfloat162 t = __halves2bfloat162(__float2bfloat16(x), __float2bfloat16(y));
    return *reinterpret_cast<uint32_t*>(&t);
}

// ---------------------------------------------------------------------------
// split3: fp32 [R,1024] -> bf16 [R,3072]
// activations (0,1): [hi | lo | hi];  weights (2,3,4): [hi | hi | lo]
// ---------------------------------------------------------------------------
template <int WHICH>
__global__ void split3(const float* __restrict__ src, int total2) {
    __nv_bfloat16* dst = (WHICH == 0) ? g_Aq : (WHICH == 1) ? g_Akv :
                         (WHICH == 2) ? g_Wqc : (WHICH == 3) ? g_Wkvc : g_W0c;
    int idx = blockIdx.x * blockDim.x + threadIdx.x;
    if (idx >= total2) return;
    int r  = idx >> 9;
    int c2 = (idx & 511) << 1;
    float2 v = *reinterpret_cast<const float2*>(src + ((size_t)r << 10) + c2);
    __nv_bfloat16 h0 = __float2bfloat16(v.x), h1 = __float2bfloat16(v.y);
    __nv_bfloat16 l0 = __float2bfloat16(v.x - __bfloat162float(h0));
    __nv_bfloat16 l1 = __float2bfloat16(v.y - __bfloat162float(h1));
    size_t o = (size_t)r * K3;
    __nv_bfloat162 hh = __halves2bfloat162(h0, h1);
    __nv_bfloat162 ll = __halves2bfloat162(l0, l1);
    if (WHICH <= 1) {
        *reinterpret_cast<__nv_bfloat162*>(dst + o + c2)        = hh;
        *reinterpret_cast<__nv_bfloat162*>(dst + o + 1024 + c2) = ll;
        *reinterpret_cast<__nv_bfloat162*>(dst + o + 2048 + c2) = hh;
    } else {
        *reinterpret_cast<__nv_bfloat162*>(dst + o + c2)        = hh;
        *reinterpret_cast<__nv_bfloat162*>(dst + o + 1024 + c2) = hh;
        *reinterpret_cast<__nv_bfloat162*>(dst + o + 2048 + c2) = ll;
    }
}

// ---------------------------------------------------------------------------
// mma.sync bf16 TN GEMM, 128x128 tile, BK=32, 8 warps (2x4), warp 64x32.
// 3-stage ring (61.4KB -> 2 CTAs/SM), ONE barrier per chunk, top-issued loads.
// ---------------------------------------------------------------------------
#define NCH         (K3 / 32)            // 96
#define ROWB        80                   // 32 bf16 = 64B data + 16B pad
#define TILE_B      (128 * ROWB)         // 10240
#define STAGE_B     (2 * TILE_B)         // 20480
#define GEMM_SMEM   (3 * STAGE_B)        // 61440

template <int MODE>
__global__ __launch_bounds__(256, 2) void gemm_mma(float* __restrict__ C) {
    extern __shared__ char smem[];
    const uint32_t sb = smem_u32(smem);
    const int tid = threadIdx.x, wid = tid >> 5, lane = tid & 31;
    const int wm = wid >> 2, wn = wid & 3;
    const int m0 = blockIdx.y * 128, n0 = blockIdx.x * 128;

    const __nv_bfloat16* Ag = (MODE == 0) ? g_Aq : (MODE == 1) ? g_Akv : g_Oc;
    const __nv_bfloat16* Bg = (MODE == 0) ? g_Wqc : (MODE == 1) ? g_Wkvc : g_W0c;
    Ag += (size_t)m0 * K3;
    Bg += (size_t)n0 * K3;

    float acc[4][4][4];
#pragma unroll
    for (int i = 0; i < 4; i++)
#pragma unroll
        for (int j = 0; j < 4; j++)
#pragma unroll
            for (int e = 0; e < 4; e++) acc[i][j][e] = 0.0f;

    auto load_stage = [&](int ch, int s) {
        uint32_t base = sb + s * STAGE_B;
#pragma unroll
        for (int t = 0; t < 4; t++) {
            int idx = tid + t * 256;            // 0..1023
            int op  = idx >> 9;                 // 0=A,1=B
            int rem = idx & 511;
            int row = rem >> 2, kc = rem & 3;
            const __nv_bfloat16* src = op ? Bg : Ag;
            cp_async16(base + op * TILE_B + row * ROWB + kc * 16,
                       src + (size_t)row * K3 + ch * 32 + kc * 8);
        }
        CP_COMMIT();
    };

    load_stage(0, 0);
    load_stage(1, 1);

    const uint32_t a_row = (uint32_t)(wm * 64 + (lane & 15));
    const uint32_t a_kb  = (uint32_t)(((lane >> 4) & 1) * 16);
    const uint32_t b_row = (uint32_t)(wn * 32 + (lane & 7) + ((lane >> 4) & 1) * 8);
    const uint32_t b_kb  = (uint32_t)(((lane >> 3) & 1) * 16);

    for (int ch = 0; ch < NCH; ch++) {
        if (ch + 1 < NCH) { CP_WAIT(1); } else { CP_WAIT(0); }
        __syncthreads();
        if (ch + 2 < NCH) load_stage(ch + 2, (ch + 2) % 3);

        uint32_t aBase = sb + (ch % 3) * STAGE_B;
        uint32_t bBase = aBase + TILE_B;
#pragma unroll
        for (int ks = 0; ks < 2; ks++) {
            uint32_t a[4][4], b[4][2];
#pragma unroll
            for (int i = 0; i < 4; i++) {
                uint32_t addr = aBase + (a_row + i * 16) * ROWB + ks * 32 + a_kb;
                ldmatrix_x4(a[i][0], a[i][1], a[i][2], a[i][3], addr);
            }
#pragma unroll
            for (int j2 = 0; j2 < 2; j2++) {
                uint32_t r0, r1, r2, r3;
                uint32_t addr = bBase + (b_row + j2 * 16) * ROWB + ks * 32 + b_kb;
                ldmatrix_x4(r0, r1, r2, r3, addr);
                b[j2 * 2][0] = r0; b[j2 * 2][1] = r1;
                b[j2 * 2 + 1][0] = r2; b[j2 * 2 + 1][1] = r3;
            }
#pragma unroll
            for (int i = 0; i < 4; i++)
#pragma unroll
                for (int j = 0; j < 4; j++)
                    mma_bf16(acc[i][j], a[i][0], a[i][1], a[i][2], a[i][3], b[j][0], b[j][1]);
        }
    }

    const int g = lane >> 2, tq = lane & 3;
#pragma unroll
    for (int i = 0; i < 4; i++) {
#pragma unroll
        for (int e = 0; e < 2; e++) {
            int m = m0 + wm * 64 + i * 16 + g + e * 8;
            int b = m >> 11;
            int t = m & 2047;
#pragma unroll
            for (int j = 0; j < 4; j++) {
#pragma unroll
                for (int x = 0; x < 2; x++) {
                    int n = n0 + wn * 32 + j * 8 + tq * 2 + x;
                    float v = acc[i][j][e * 2 + x];
                    if (MODE == 0) {
                        int d = n >> 4, h = n & 15;
                        size_t a5 = ((((size_t)b * HEADS + h) * SEQ + t) << 6) + d;
                        float vs = v * 0.125f;
                        __nv_bfloat16 hi = __float2bfloat16(vs);
                        g_Qh[a5] = hi;
                        g_Ql[a5] = __float2bfloat16(vs - __bfloat162float(hi));
                    } else if (MODE == 1) {
                        int h = n & 15, kk = (n >> 4) & 1, d = n >> 5;
                        size_t a5 = ((((size_t)b * HEADS + h) * SEQ + t) << 6) + d;
                        __nv_bfloat16 hi = __float2bfloat16(v);
                        __nv_bfloat16 lo = __float2bfloat16(v - __bfloat162float(hi));
                        if (kk) { g_Vh[a5] = hi; g_Vl[a5] = lo; }
                        else    { g_Kh[a5] = hi; g_Kl[a5] = lo; }
                    } else {
                        C[(size_t)m * 1024 + n] = v;
                    }
                }
            }
        }
    }
}

// ---------------------------------------------------------------------------
// Flash attention on mma.sync. CTA: 128 q-rows, 8 warps, key tiles of 64.
// 3-stage KV ring, ONE barrier per tile; forced 2 CTAs/SM.
// ---------------------------------------------------------------------------
#define AROWB    144
#define ATILE_B  (64 * AROWB)            // 9216
#define ASTAGE_B (4 * ATILE_B)           // 36864  (Kh|Kl|Vh|Vl)
#define ATTN_SMEM (3 * ASTAGE_B)         // 110592

__global__ __launch_bounds__(256, 2) void attn_mma() {
    extern __shared__ char smem[];
    const uint32_t sb = smem_u32(smem);
    const int tid = threadIdx.x, wid = tid >> 5, lane = tid & 31;
    const int g = lane >> 2, tq = lane & 3;
    const int bh = blockIdx.y;
    const int t0 = blockIdx.x << 7;

    const size_t bhoff = (size_t)bh * SEQ * DHEAD;
    const __nv_bfloat16* Qh = g_Qh + bhoff + (size_t)t0 * DHEAD;
    const __nv_bfloat16* Ql = g_Ql + bhoff + (size_t)t0 * DHEAD;
    const __nv_bfloat16* Kh = g_Kh + bhoff;
    const __nv_bfloat16* Kl = g_Kl + bhoff;
    const __nv_bfloat16* Vh = g_Vh + bhoff;
    const __nv_bfloat16* Vl = g_Vl + bhoff;

    // ---- Stage Q in stage-0/1 smem and extract fragments
#pragma unroll
    for (int t = 0; t < 8; t++) {
        int idx = tid + t * 256;
        int mat = idx >> 10;
        int r   = (idx >> 3) & 127;
        int ck  = idx & 7;
        const __nv_bfloat16* src = mat ? Ql : Qh;
        cp_async16(sb + mat * (2 * ATILE_B) + r * AROWB + ck * 16,
                   src + (size_t)r * DHEAD + ck * 8);
    }
    CP_COMMIT();
    CP_WAIT(0);
    __syncthreads();

    uint32_t qh[4][4], ql[4][4];
    {
        uint32_t qrow = (uint32_t)(wid * 16 + (lane & 15));
        uint32_t kb   = (uint32_t)(((lane >> 4) & 1) * 16);
#pragma unroll
        for (int ks = 0; ks < 4; ks++) {
            uint32_t addr = sb + qrow * AROWB + ks * 32 + kb;
            ldmatrix_x4(qh[ks][0], qh[ks][1], qh[ks][2], qh[ks][3], addr);
            ldmatrix_x4(ql[ks][0], ql[ks][1], ql[ks][2], ql[ks][3],
                        addr + 2 * ATILE_B);
        }
    }
    __syncthreads();

    auto load_kv = [&](int jt, int s) {
        uint32_t base = sb + s * ASTAGE_B;
        const __nv_bfloat16* ptrs[4] = {Kh, Kl, Vh, Vl};
#pragma unroll
        for (int t = 0; t < 8; t++) {
            int idx = tid + t * 256;
            int mat = idx >> 9;
            int r   = (idx >> 3) & 63;
            int ck  = idx & 7;
            cp_async16(base + mat * ATILE_B + r * AROWB + ck * 16,
                       ptrs[mat] + (size_t)(jt * 64 + r) * DHEAD + ck * 8);
        }
        CP_COMMIT();
    };

    load_kv(0, 0);
    load_kv(1, 1);

    float oacc[8][4];
#pragma unroll
    for (int j = 0; j < 8; j++)
#pragma unroll
        for (int e = 0; e < 4; e++) oacc[j][e] = 0.0f;
    float mr0 = -1e30f, mr1 = -1e30f, lr0 = 0.0f, lr1 = 0.0f;

    const uint32_t kb_row = (uint32_t)((lane & 7) + ((lane >> 4) & 1) * 8);
    const uint32_t kb_kb  = (uint32_t)(((lane >> 3) & 1) * 16);
    const uint32_t v_row  = (uint32_t)((lane & 7) + ((lane >> 3) & 1) * 8);
    const uint32_t v_cb   = (uint32_t)(((lane >> 4) & 1) * 8 * 2);

    for (int jt = 0; jt < SEQ / 64; jt++) {
        if (jt + 1 < SEQ / 64) { CP_WAIT(1); } else { CP_WAIT(0); }
        __syncthreads();
        if (jt + 2 < SEQ / 64) load_kv(jt + 2, (jt + 2) % 3);
        uint32_t st = sb + (jt % 3) * ASTAGE_B;

        // ---- S = Qh*Kh + Ql*Kh + Qh*Kl
        float sacc[8][4];
#pragma unroll
        for (int j = 0; j < 8; j++)
#pragma unroll
            for (int e = 0; e < 4; e++) sacc[j][e] = 0.0f;
#pragma unroll
        for (int ks = 0; ks < 4; ks++) {
            uint32_t bt[8][2];
#pragma unroll
            for (int j2 = 0; j2 < 4; j2++) {
                uint32_t r0, r1, r2, r3;
                uint32_t addr = st + (kb_row + j2 * 16) * AROWB + ks * 32 + kb_kb;
                ldmatrix_x4(r0, r1, r2, r3, addr);
                bt[j2 * 2][0] = r0; bt[j2 * 2][1] = r1;
                bt[j2 * 2 + 1][0] = r2; bt[j2 * 2 + 1][1] = r3;
            }
#pragma unroll
            for (int j = 0; j < 8; j++)
                mma_bf16(sacc[j], qh[ks][0], qh[ks][1], qh[ks][2], qh[ks][3],
                         bt[j][0], bt[j][1]);
#pragma unroll
            for (int j = 0; j < 8; j++)
                mma_bf16(sacc[j], ql[ks][0], ql[ks][1], ql[ks][2], ql[ks][3],
                         bt[j][0], bt[j][1]);
#pragma unroll
            for (int j2 = 0; j2 < 4; j2++) {
                uint32_t r0, r1, r2, r3;
                uint32_t addr = st + ATILE_B + (kb_row + j2 * 16) * AROWB + ks * 32 + kb_kb;
                ldmatrix_x4(r0, r1, r2, r3, addr);
                bt[j2 * 2][0] = r0; bt[j2 * 2][1] = r1;
                bt[j2 * 2 + 1][0] = r2; bt[j2 * 2 + 1][1] = r3;
            }
#pragma unroll
            for (int j = 0; j < 8; j++)
                mma_bf16(sacc[j], qh[ks][0], qh[ks][1], qh[ks][2], qh[ks][3],
                         bt[j][0], bt[j][1]);
        }

        // ---- online softmax
        float mx0 = -1e30f, mx1 = -1e30f;
#pragma unroll
        for (int j = 0; j < 8; j++) {
            mx0 = fmaxf(mx0, fmaxf(sacc[j][0], sacc[j][1]));
            mx1 = fmaxf(mx1, fmaxf(sacc[j][2], sacc[j][3]));
        }
        mx0 = fmaxf(mx0, __shfl_xor_sync(0xffffffffu, mx0, 1));
        mx0 = fmaxf(mx0, __shfl_xor_sync(0xffffffffu, mx0, 2));
        mx1 = fmaxf(mx1, __shfl_xor_sync(0xffffffffu, mx1, 1));
        mx1 = fmaxf(mx1, __shfl_xor_sync(0xffffffffu, mx1, 2));
        float mn0 = fmaxf(mr0, mx0), mn1 = fmaxf(mr1, mx1);
        float al0 = __expf(mr0 - mn0), al1 = __expf(mr1 - mn1);
        mr0 = mn0; mr1 = mn1;
        float sum0 = 0.0f, sum1 = 0.0f;
#pragma unroll
        for (int j = 0; j < 8; j++) {
            sacc[j][0] = __expf(sacc[j][0] - mn0);
            sacc[j][1] = __expf(sacc[j][1] - mn0);
            sacc[j][2] = __expf(sacc[j][2] - mn1);
            sacc[j][3] = __expf(sacc[j][3] - mn1);
            sum0 += sacc[j][0] + sacc[j][1];
            sum1 += sacc[j][2] + sacc[j][3];
        }
        sum0 += __shfl_xor_sync(0xffffffffu, sum0, 1);
        sum0 += __shfl_xor_sync(0xffffffffu, sum0, 2);
        sum1 += __shfl_xor_sync(0xffffffffu, sum1, 1);
        sum1 += __shfl_xor_sync(0xffffffffu, sum1, 2);
        lr0 = lr0 * al0 + sum0;
        lr1 = lr1 * al1 + sum1;
#pragma unroll
        for (int j = 0; j < 8; j++) {
            oacc[j][0] *= al0; oacc[j][1] *= al0;
            oacc[j][2] *= al1; oacc[j][3] *= al1;
        }

        // ---- O += Ph*Vh + Pl*Vh + Ph*Vl
#pragma unroll
        for (int cs = 0; cs < 4; cs++) {
            int j0 = cs * 2, j1 = cs * 2 + 1;
            uint32_t ph[4], pl[4];
            {
                float p00 = sacc[j0][0], p01 = sacc[j0][1];
                float p02 = sacc[j0][2], p03 = sacc[j0][3];
                float p10 = sacc[j1][0], p11 = sacc[j1][1];
                float p12 = sacc[j1][2], p13 = sacc[j1][3];
                ph[0] = pack_bf16x2(p00, p01);
                ph[1] = pack_bf16x2(p02, p03);
                ph[2] = pack_bf16x2(p10, p11);
                ph[3] = pack_bf16x2(p12, p13);
                __nv_bfloat162 h;
                h = *reinterpret_cast<__nv_bfloat162*>(&ph[0]);
                pl[0] = pack_bf16x2(p00 - __bfloat162float(h.x), p01 - __bfloat162float(h.y));
                h = *reinterpret_cast<__nv_bfloat162*>(&ph[1]);
                pl[1] = pack_bf16x2(p02 - __bfloat162float(h.x), p03 - __bfloat162float(h.y));
                h = *reinterpret_cast<__nv_bfloat162*>(&ph[2]);
                pl[2] = pack_bf16x2(p10 - __bfloat162float(h.x), p11 - __bfloat162float(h.y));
                h = *reinterpret_cast<__nv_bfloat162*>(&ph[3]);
                pl[3] = pack_bf16x2(p12 - __bfloat162float(h.x), p13 - __bfloat162float(h.y));
            }
            uint32_t vt[8][2];
#pragma unroll
            for (int jd2 = 0; jd2 < 4; jd2++) {
                uint32_t r0, r1, r2, r3;
                uint32_t addr = st + 2 * ATILE_B + (cs * 16 + v_row) * AROWB
                              + jd2 * 32 + v_cb;
                ldmatrix_x4_trans(r0, r1, r2, r3, addr);
                vt[jd2 * 2][0] = r0; vt[jd2 * 2][1] = r1;
                vt[jd2 * 2 + 1][0] = r2; vt[jd2 * 2 + 1][1] = r3;
            }
#pragma unroll
            for (int jd = 0; jd < 8; jd++)
                mma_bf16(oacc[jd], ph[0], ph[1], ph[2], ph[3], vt[jd][0], vt[jd][1]);
#pragma unroll
            for (int jd = 0; jd < 8; jd++)
                mma_bf16(oacc[jd], pl[0], pl[1], pl[2], pl[3], vt[jd][0], vt[jd][1]);
#pragma unroll
            for (int jd2 = 0; jd2 < 4; jd2++) {
                uint32_t r0, r1, r2, r3;
                uint32_t addr = st + 3 * ATILE_B + (cs * 16 + v_row) * AROWB
                              + jd2 * 32 + v_cb;
                ldmatrix_x4_trans(r0, r1, r2, r3, addr);
                vt[jd2 * 2][0] = r0; vt[jd2 * 2][1] = r1;
                vt[jd2 * 2 + 1][0] = r2; vt[jd2 * 2 + 1][1] = r3;
            }
#pragma unroll
            for (int jd = 0; jd < 8; jd++)
                mma_bf16(oacc[jd], ph[0], ph[1], ph[2], ph[3], vt[jd][0], vt[jd][1]);
        }
    }

    // ---- epilogue
    const int bq = bh >> 4;
    const int h  = bh & 15;
    float inv0 = 1.0f / lr0, inv1 = 1.0f / lr1;
#pragma unroll
    for (int e = 0; e < 2; e++) {
        int trow = t0 + wid * 16 + g + e * 8;
        float inv = e ? inv1 : inv0;
        size_t rowbase = (size_t)(bq * SEQ + trow) * K3 + h * DHEAD;
#pragma unroll
        for (int jd = 0; jd < 8; jd++) {
            int d = jd * 8 + tq * 2;
            float v0 = oacc[jd][e * 2 + 0] * inv;
            float v1 = oacc[jd][e * 2 + 1] * inv;
            __nv_bfloat16 h0 = __float2bfloat16(v0), h1 = __float2bfloat16(v1);
            __nv_bfloat16 l0 = __float2bfloat16(v0 - __bfloat162float(h0));
            __nv_bfloat16 l1 = __float2bfloat16(v1 - __bfloat162float(h1));
            __nv_bfloat162 hh = __halves2bfloat162(h0, h1);
            __nv_bfloat162 ll = __halves2bfloat162(l0, l1);
            *reinterpret_cast<__nv_bfloat162*>(g_Oc + rowbase + d)        = hh;
            *reinterpret_cast<__nv_bfloat162*>(g_Oc + rowbase + 1024 + d) = ll;
            *reinterpret_cast<__nv_bfloat162*>(g_Oc + rowbase + 2048 + d) = hh;
        }
    }
}

// ---------------------------------------------------------------------------
extern "C" void kernel_launch(void* const* d_in, const int* in_sizes, int n_in,
                              void* d_out, int out_size) {
    const float* q   = (const float*)d_in[0];
    const float* kv  = (const float*)d_in[1];
    const float* Wq  = (const float*)d_in[2];
    const float* Wkv = (const float*)d_in[3];
    const float* W0  = (const float*)d_in[4];
    float* out = (float*)d_out;
    (void)in_sizes; (void)n_in; (void)out_size;

    (void)cudaFuncSetAttribute(attn_mma, cudaFuncAttributeMaxDynamicSharedMemorySize, ATTN_SMEM);
    (void)cudaFuncSetAttribute(gemm_mma<0>, cudaFuncAttributeMaxDynamicSharedMemorySize, GEMM_SMEM);
    (void)cudaFuncSetAttribute(gemm_mma<1>, cudaFuncAttributeMaxDynamicSharedMemorySize, GEMM_SMEM);
    (void)cudaFuncSetAttribute(gemm_mma<2>, cudaFuncAttributeMaxDynamicSharedMemorySize, GEMM_SMEM);

    split3<0><<<(MROWS * 512 + 255) / 256, 256>>>(q,   MROWS * 512);
    split3<1><<<(MROWS * 512 + 255) / 256, 256>>>(kv,  MROWS * 512);
    split3<2><<<(1024 * 512 + 255) / 256, 256>>>(Wq,  1024 * 512);
    split3<3><<<(2048 * 512 + 255) / 256, 256>>>(Wkv, 2048 * 512);
    split3<4><<<(1024 * 512 + 255) / 256, 256>>>(W0,  1024 * 512);

    gemm_mma<0><<<dim3(EDIM / 128, MROWS / 128), 256, GEMM_SMEM>>>(nullptr);
    gemm_mma<1><<<dim3(2 * EDIM / 128, MROWS / 128), 256, GEMM_SMEM>>>(nullptr);
    attn_mma<<<dim3(SEQ / 128, BATCH * HEADS), 256, ATTN_SMEM>>>();
    gemm_mma<2><<<dim3(DMODEL / 128, MROWS / 128), 256, GEMM_SMEM>>>(out);
}

// round 11
// speedup vs baseline: 1.2026x; 1.2026x over previous
#include <cuda_runtime.h>
#include <cuda_bf16.h>
#include <cuda_fp16.h>
#include <cstdint>

// Problem constants
#define BATCH   4
#define SEQ     2048
#define DMODEL  1024
#define HEADS   16
#define DHEAD   64
#define EDIM    1024
#define MROWS   (BATCH * SEQ)     // 8192
#define K3      3072              // split-bf16 K' = 3*1024

// ---------------------------------------------------------------------------
// Scratch (device globals; no allocation allowed)
// ---------------------------------------------------------------------------
// Attention operands (fp16). Q pre-scaled by 0.125, split hi+lo; K/V plain fp16.
__device__ __align__(256) __half g_Qh[(size_t)BATCH * HEADS * SEQ * DHEAD];
__device__ __align__(256) __half g_Ql[(size_t)BATCH * HEADS * SEQ * DHEAD];
__device__ __align__(256) __half g_K [(size_t)BATCH * HEADS * SEQ * DHEAD];
__device__ __align__(256) __half g_V [(size_t)BATCH * HEADS * SEQ * DHEAD];
// split-bf16 GEMM operands: [rows, 3072]
__device__ __align__(256) __nv_bfloat16 g_Aq [(size_t)MROWS * K3];
__device__ __align__(256) __nv_bfloat16 g_Akv[(size_t)MROWS * K3];
__device__ __align__(256) __nv_bfloat16 g_Oc [(size_t)MROWS * K3];
__device__ __align__(256) __nv_bfloat16 g_Wqc [(size_t)1024 * K3];
__device__ __align__(256) __nv_bfloat16 g_Wkvc[(size_t)2048 * K3];
__device__ __align__(256) __nv_bfloat16 g_W0c [(size_t)1024 * K3];

// ---------------------------------------------------------------------------
// Helpers
// ---------------------------------------------------------------------------
__device__ __forceinline__ uint32_t smem_u32(const void* p) {
    uint32_t a;
    asm("{ .reg .u64 t; cvta.to.shared.u64 t, %1; cvt.u32.u64 %0, t; }" : "=r"(a) : "l"(p));
    return a;
}
__device__ __forceinline__ void cp_async16(uint32_t smem_addr, const void* gptr) {
    asm volatile("cp.async.cg.shared.global [%0], [%1], 16;" :: "r"(smem_addr), "l"(gptr));
}
#define CP_COMMIT() asm volatile("cp.async.commit_group;" ::: "memory")
#define CP_WAIT(n)  asm volatile("cp.async.wait_group %0;" :: "n"(n) : "memory")

__device__ __forceinline__ void ldmatrix_x4(uint32_t& r0, uint32_t& r1, uint32_t& r2,
                                            uint32_t& r3, uint32_t addr) {
    asm volatile("ldmatrix.sync.aligned.m8n8.x4.shared.b16 {%0,%1,%2,%3}, [%4];"
                 : "=r"(r0), "=r"(r1), "=r"(r2), "=r"(r3) : "r"(addr));
}
__device__ __forceinline__ void ldmatrix_x4_trans(uint32_t& r0, uint32_t& r1, uint32_t& r2,
                                                  uint32_t& r3, uint32_t addr) {
    asm volatile("ldmatrix.sync.aligned.m8n8.x4.trans.shared.b16 {%0,%1,%2,%3}, [%4];"
                 : "=r"(r0), "=r"(r1), "=r"(r2), "=r"(r3) : "r"(addr));
}
__device__ __forceinline__ void mma_bf16(float* c,
                                         uint32_t a0, uint32_t a1, uint32_t a2, uint32_t a3,
                                         uint32_t b0, uint32_t b1) {
    asm volatile(
        "mma.sync.aligned.m16n8k16.row.col.f32.bf16.bf16.f32 "
        "{%0,%1,%2,%3}, {%4,%5,%6,%7}, {%8,%9}, {%0,%1,%2,%3};"
        : "+f"(c[0]), "+f"(c[1]), "+f"(c[2]), "+f"(c[3])
        : "r"(a0), "r"(a1), "r"(a2), "r"(a3), "r"(b0), "r"(b1));
}
__device__ __forceinline__ void mma_f16(float* c,
                                        uint32_t a0, uint32_t a1, uint32_t a2, uint32_t a3,
                                        uint32_t b0, uint32_t b1) {
    asm volatile(
        "mma.sync.aligned.m16n8k16.row.col.f32.f16.f16.f32 "
        "{%0,%1,%2,%3}, {%4,%5,%6,%7}, {%8,%9}, {%0,%1,%2,%3};"
        : "+f"(c[0]), "+f"(c[1]), "+f"(c[2]), "+f"(c[3])
        : "r"(a0), "r"(a1), "r"(a2), "r"(a3), "r"(b0), "r"(b1));
}
__device__ __forceinline__ uint32_t pack_h2(float x, float y) {
    __half2 t = __halves2half2(__float2half(x), __float2half(y));
    return *reinterpret_cast<uint32_t*>(&t);
}

// ---------------------------------------------------------------------------
// split3: fp32 [R,1024] -> bf16 [R,3072]
// activations (0,1): [hi | lo | hi];  weights (2,3,4): [hi | hi | lo]
// ---------------------------------------------------------------------------
template <int WHICH>
__global__ void split3(const float* __restrict__ src, int total2) {
    __nv_bfloat16* dst = (WHICH == 0) ? g_Aq : (WHICH == 1) ? g_Akv :
                         (WHICH == 2) ? g_Wqc : (WHICH == 3) ? g_Wkvc : g_W0c;
    int idx = blockIdx.x * blockDim.x + threadIdx.x;
    if (idx >= total2) return;
    int r  = idx >> 9;
    int c2 = (idx & 511) << 1;
    float2 v = *reinterpret_cast<const float2*>(src + ((size_t)r << 10) + c2);
    __nv_bfloat16 h0 = __float2bfloat16(v.x), h1 = __float2bfloat16(v.y);
    __nv_bfloat16 l0 = __float2bfloat16(v.x - __bfloat162float(h0));
    __nv_bfloat16 l1 = __float2bfloat16(v.y - __bfloat162float(h1));
    size_t o = (size_t)r * K3;
    __nv_bfloat162 hh = __halves2bfloat162(h0, h1);
    __nv_bfloat162 ll = __halves2bfloat162(l0, l1);
    if (WHICH <= 1) {
        *reinterpret_cast<__nv_bfloat162*>(dst + o + c2)        = hh;
        *reinterpret_cast<__nv_bfloat162*>(dst + o + 1024 + c2) = ll;
        *reinterpret_cast<__nv_bfloat162*>(dst + o + 2048 + c2) = hh;
    } else {
        *reinterpret_cast<__nv_bfloat162*>(dst + o + c2)        = hh;
        *reinterpret_cast<__nv_bfloat162*>(dst + o + 1024 + c2) = hh;
        *reinterpret_cast<__nv_bfloat162*>(dst + o + 2048 + c2) = ll;
    }
}

// ---------------------------------------------------------------------------
// mma.sync bf16 TN GEMM, 128x128 tile, BK=64, 8 warps (2x4), warp 64x32.
// (round-8 best config) 3-stage ring, ONE barrier per chunk, top-issued loads.
// MODE 0: scatter n=(d*16+h) -> g_Qh/g_Ql fp16 (pre-scaled 0.125)
// MODE 1: scatter n=(d*32+kk*16+h) -> g_K or g_V (plain fp16)
// MODE 2: C[m*1024+n] = v (d_out)
// ---------------------------------------------------------------------------
#define NCH         (K3 / 64)            // 48
#define ROWB        144                  // 64 bf16 = 128B data + 16B pad
#define TILE_B      (128 * ROWB)         // 18432
#define STAGE_B     (2 * TILE_B)         // 36864
#define GEMM_SMEM   (3 * STAGE_B)        // 110592

template <int MODE>
__global__ __launch_bounds__(256) void gemm_mma(float* __restrict__ C) {
    extern __shared__ char smem[];
    const uint32_t sb = smem_u32(smem);
    const int tid = threadIdx.x, wid = tid >> 5, lane = tid & 31;
    const int wm = wid >> 2, wn = wid & 3;
    const int m0 = blockIdx.y * 128, n0 = blockIdx.x * 128;

    const __nv_bfloat16* Ag = (MODE == 0) ? g_Aq : (MODE == 1) ? g_Akv : g_Oc;
    const __nv_bfloat16* Bg = (MODE == 0) ? g_Wqc : (MODE == 1) ? g_Wkvc : g_W0c;
    Ag += (size_t)m0 * K3;
    Bg += (size_t)n0 * K3;

    float acc[4][4][4];
#pragma unroll
    for (int i = 0; i < 4; i++)
#pragma unroll
        for (int j = 0; j < 4; j++)
#pragma unroll
            for (int e = 0; e < 4; e++) acc[i][j][e] = 0.0f;

    auto load_stage = [&](int ch, int s) {
        uint32_t base = sb + s * STAGE_B;
#pragma unroll
        for (int t = 0; t < 8; t++) {
            int idx = tid + t * 256;            // 0..2047
            int op  = idx >> 10;                // 0=A,1=B
            int row = (idx >> 3) & 127;
            int ck  = idx & 7;
            const __nv_bfloat16* src = op ? Bg : Ag;
            cp_async16(base + op * TILE_B + row * ROWB + ck * 16,
                       src + (size_t)row * K3 + ch * 64 + ck * 8);
        }
        CP_COMMIT();
    };

    load_stage(0, 0);
    load_stage(1, 1);

    const uint32_t a_row = (uint32_t)(wm * 64 + (lane & 15));
    const uint32_t a_kb  = (uint32_t)(((lane >> 4) & 1) * 16);
    const uint32_t b_row = (uint32_t)(wn * 32 + (lane & 7) + ((lane >> 4) & 1) * 8);
    const uint32_t b_kb  = (uint32_t)(((lane >> 3) & 1) * 16);

    for (int ch = 0; ch < NCH; ch++) {
        if (ch + 1 < NCH) { CP_WAIT(1); } else { CP_WAIT(0); }
        __syncthreads();
        if (ch + 2 < NCH) load_stage(ch + 2, (ch + 2) % 3);

        uint32_t aBase = sb + (ch % 3) * STAGE_B;
        uint32_t bBase = aBase + TILE_B;
#pragma unroll
        for (int ks = 0; ks < 4; ks++) {
            uint32_t a[4][4], b[4][2];
#pragma unroll
            for (int i = 0; i < 4; i++) {
                uint32_t addr = aBase + (a_row + i * 16) * ROWB + ks * 32 + a_kb;
                ldmatrix_x4(a[i][0], a[i][1], a[i][2], a[i][3], addr);
            }
#pragma unroll
            for (int j2 = 0; j2 < 2; j2++) {
                uint32_t r0, r1, r2, r3;
                uint32_t addr = bBase + (b_row + j2 * 16) * ROWB + ks * 32 + b_kb;
                ldmatrix_x4(r0, r1, r2, r3, addr);
                b[j2 * 2][0] = r0; b[j2 * 2][1] = r1;
                b[j2 * 2 + 1][0] = r2; b[j2 * 2 + 1][1] = r3;
            }
#pragma unroll
            for (int i = 0; i < 4; i++)
#pragma unroll
                for (int j = 0; j < 4; j++)
                    mma_bf16(acc[i][j], a[i][0], a[i][1], a[i][2], a[i][3], b[j][0], b[j][1]);
        }
    }

    const int g = lane >> 2, tq = lane & 3;
#pragma unroll
    for (int i = 0; i < 4; i++) {
#pragma unroll
        for (int e = 0; e < 2; e++) {
            int m = m0 + wm * 64 + i * 16 + g + e * 8;
            int b = m >> 11;
            int t = m & 2047;
#pragma unroll
            for (int j = 0; j < 4; j++) {
#pragma unroll
                for (int x = 0; x < 2; x++) {
                    int n = n0 + wn * 32 + j * 8 + tq * 2 + x;
                    float v = acc[i][j][e * 2 + x];
                    if (MODE == 0) {
                        int d = n >> 4, h = n & 15;
                        size_t a5 = ((((size_t)b * HEADS + h) * SEQ + t) << 6) + d;
                        float vs = v * 0.125f;
                        __half hi = __float2half(vs);
                        g_Qh[a5] = hi;
                        g_Ql[a5] = __float2half(vs - __half2float(hi));
                    } else if (MODE == 1) {
                        int h = n & 15, kk = (n >> 4) & 1, d = n >> 5;
                        size_t a5 = ((((size_t)b * HEADS + h) * SEQ + t) << 6) + d;
                        if (kk) g_V[a5] = __float2half(v);
                        else    g_K[a5] = __float2half(v);
                    } else {
                        C[(size_t)m * 1024 + n] = v;
                    }
                }
            }
        }
    }
}

// ---------------------------------------------------------------------------
// Flash attention, fp16 2-product asymmetric split:
//   S = (Qh + Ql) . K      (K plain fp16)
//   O = (Ph + Pl) . V      (V plain fp16)
// CTA: 128 q-rows, 8 warps, key tiles of 64; 3-stage KV ring (K|V per stage),
// ONE barrier per tile, loads issued at top of iteration.
// ---------------------------------------------------------------------------
#define AROWB    144
#define ATILE_B  (64 * AROWB)            // 9216
#define ASTAGE_B (2 * ATILE_B)           // 18432  (K | V)
#define ATTN_SMEM (3 * ASTAGE_B)         // 55296

__global__ __launch_bounds__(256) void attn_mma() {
    extern __shared__ char smem[];
    const uint32_t sb = smem_u32(smem);
    const int tid = threadIdx.x, wid = tid >> 5, lane = tid & 31;
    const int g = lane >> 2, tq = lane & 3;
    const int bh = blockIdx.y;
    const int t0 = blockIdx.x << 7;

    const size_t bhoff = (size_t)bh * SEQ * DHEAD;
    const __half* Qh = g_Qh + bhoff + (size_t)t0 * DHEAD;
    const __half* Ql = g_Ql + bhoff + (size_t)t0 * DHEAD;
    const __half* Kg = g_K + bhoff;
    const __half* Vg = g_V + bhoff;

    // ---- Stage Q (hi at 0, lo at +ATILE_B*2) and extract fragments
#pragma unroll
    for (int t = 0; t < 8; t++) {
        int idx = tid + t * 256;             // 0..2047
        int mat = idx >> 10;                 // 0=hi,1=lo
        int r   = (idx >> 3) & 127;
        int ck  = idx & 7;
        const __half* src = mat ? Ql : Qh;
        cp_async16(sb + mat * (2 * ATILE_B) + r * AROWB + ck * 16,
                   src + (size_t)r * DHEAD + ck * 8);
    }
    CP_COMMIT();
    CP_WAIT(0);
    __syncthreads();

    uint32_t qh[4][4], ql[4][4];
    {
        uint32_t qrow = (uint32_t)(wid * 16 + (lane & 15));
        uint32_t kb   = (uint32_t)(((lane >> 4) & 1) * 16);
#pragma unroll
        for (int ks = 0; ks < 4; ks++) {
            uint32_t addr = sb + qrow * AROWB + ks * 32 + kb;
            ldmatrix_x4(qh[ks][0], qh[ks][1], qh[ks][2], qh[ks][3], addr);
            ldmatrix_x4(ql[ks][0], ql[ks][1], ql[ks][2], ql[ks][3],
                        addr + 2 * ATILE_B);
        }
    }
    __syncthreads();

    auto load_kv = [&](int jt, int s) {
        uint32_t base = sb + s * ASTAGE_B;
#pragma unroll
        for (int t = 0; t < 4; t++) {
            int idx = tid + t * 256;         // 0..1023
            int mat = idx >> 9;              // 0=K,1=V
            int r   = (idx >> 3) & 63;
            int ck  = idx & 7;
            const __half* src = mat ? Vg : Kg;
            cp_async16(base + mat * ATILE_B + r * AROWB + ck * 16,
                       src + (size_t)(jt * 64 + r) * DHEAD + ck * 8);
        }
        CP_COMMIT();
    };

    load_kv(0, 0);
    load_kv(1, 1);

    float oacc[8][4];
#pragma unroll
    for (int j = 0; j < 8; j++)
#pragma unroll
        for (int e = 0; e < 4; e++) oacc[j][e] = 0.0f;
    float mr0 = -1e30f, mr1 = -1e30f, lr0 = 0.0f, lr1 = 0.0f;

    const uint32_t kb_row = (uint32_t)((lane & 7) + ((lane >> 4) & 1) * 8);
    const uint32_t kb_kb  = (uint32_t)(((lane >> 3) & 1) * 16);
    const uint32_t v_row  = (uint32_t)((lane & 7) + ((lane >> 3) & 1) * 8);
    const uint32_t v_cb   = (uint32_t)(((lane >> 4) & 1) * 8 * 2);

    for (int jt = 0; jt < SEQ / 64; jt++) {
        if (jt + 1 < SEQ / 64) { CP_WAIT(1); } else { CP_WAIT(0); }
        __syncthreads();
        if (jt + 2 < SEQ / 64) load_kv(jt + 2, (jt + 2) % 3);
        uint32_t st = sb + (jt % 3) * ASTAGE_B;

        // ---- S = Qh*K + Ql*K
        float sacc[8][4];
#pragma unroll
        for (int j = 0; j < 8; j++)
#pragma unroll
            for (int e = 0; e < 4; e++) sacc[j][e] = 0.0f;
#pragma unroll
        for (int ks = 0; ks < 4; ks++) {
            uint32_t bt[8][2];
#pragma unroll
            for (int j2 = 0; j2 < 4; j2++) {
                uint32_t r0, r1, r2, r3;
                uint32_t addr = st + (kb_row + j2 * 16) * AROWB + ks * 32 + kb_kb;
                ldmatrix_x4(r0, r1, r2, r3, addr);
                bt[j2 * 2][0] = r0; bt[j2 * 2][1] = r1;
                bt[j2 * 2 + 1][0] = r2; bt[j2 * 2 + 1][1] = r3;
            }
#pragma unroll
            for (int j = 0; j < 8; j++)
                mma_f16(sacc[j], qh[ks][0], qh[ks][1], qh[ks][2], qh[ks][3],
                        bt[j][0], bt[j][1]);
#pragma unroll
            for (int j = 0; j < 8; j++)
                mma_f16(sacc[j], ql[ks][0], ql[ks][1], ql[ks][2], ql[ks][3],
                        bt[j][0], bt[j][1]);
        }

        // ---- online softmax
        float mx0 = -1e30f, mx1 = -1e30f;
#pragma unroll
        for (int j = 0; j < 8; j++) {
            mx0 = fmaxf(mx0, fmaxf(sacc[j][0], sacc[j][1]));
            mx1 = fmaxf(mx1, fmaxf(sacc[j][2], sacc[j][3]));
        }
        mx0 = fmaxf(mx0, __shfl_xor_sync(0xffffffffu, mx0, 1));
        mx0 = fmaxf(mx0, __shfl_xor_sync(0xffffffffu, mx0, 2));
        mx1 = fmaxf(mx1, __shfl_xor_sync(0xffffffffu, mx1, 1));
        mx1 = fmaxf(mx1, __shfl_xor_sync(0xffffffffu, mx1, 2));
        float mn0 = fmaxf(mr0, mx0), mn1 = fmaxf(mr1, mx1);
        float al0 = __expf(mr0 - mn0), al1 = __expf(mr1 - mn1);
        mr0 = mn0; mr1 = mn1;
        float sum0 = 0.0f, sum1 = 0.0f;
#pragma unroll
        for (int j = 0; j < 8; j++) {
            sacc[j][0] = __expf(sacc[j][0] - mn0);
            sacc[j][1] = __expf(sacc[j][1] - mn0);
            sacc[j][2] = __expf(sacc[j][2] - mn1);
            sacc[j][3] = __expf(sacc[j][3] - mn1);
            sum0 += sacc[j][0] + sacc[j][1];
            sum1 += sacc[j][2] + sacc[j][3];
        }
        sum0 += __shfl_xor_sync(0xffffffffu, sum0, 1);
        sum0 += __shfl_xor_sync(0xffffffffu, sum0, 2);
        sum1 += __shfl_xor_sync(0xffffffffu, sum1, 1);
        sum1 += __shfl_xor_sync(0xffffffffu, sum1, 2);
        lr0 = lr0 * al0 + sum0;
        lr1 = lr1 * al1 + sum1;
#pragma unroll
        for (int j = 0; j < 8; j++) {
            oacc[j][0] *= al0; oacc[j][1] *= al0;
            oacc[j][2] *= al1; oacc[j][3] *= al1;
        }

        // ---- O += Ph*V + Pl*V
#pragma unroll
        for (int cs = 0; cs < 4; cs++) {
            int j0 = cs * 2, j1 = cs * 2 + 1;
            uint32_t ph[4], pl[4];
            {
                float p00 = sacc[j0][0], p01 = sacc[j0][1];
                float p02 = sacc[j0][2], p03 = sacc[j0][3];
                float p10 = sacc[j1][0], p11 = sacc[j1][1];
                float p12 = sacc[j1][2], p13 = sacc[j1][3];
                ph[0] = pack_h2(p00, p01);
                ph[1] = pack_h2(p02, p03);
                ph[2] = pack_h2(p10, p11);
                ph[3] = pack_h2(p12, p13);
                __half2 h;
                h = *reinterpret_cast<__half2*>(&ph[0]);
                pl[0] = pack_h2(p00 - __half2float(h.x), p01 - __half2float(h.y));
                h = *reinterpret_cast<__half2*>(&ph[1]);
                pl[1] = pack_h2(p02 - __half2float(h.x), p03 - __half2float(h.y));
                h = *reinterpret_cast<__half2*>(&ph[2]);
                pl[2] = pack_h2(p10 - __half2float(h.x), p11 - __half2float(h.y));
                h = *reinterpret_cast<__half2*>(&ph[3]);
                pl[3] = pack_h2(p12 - __half2float(h.x), p13 - __half2float(h.y));
            }
            uint32_t vt[8][2];
#pragma unroll
            for (int jd2 = 0; jd2 < 4; jd2++) {
                uint32_t r0, r1, r2, r3;
                uint32_t addr = st + ATILE_B + (cs * 16 + v_row) * AROWB
                              + jd2 * 32 + v_cb;
                ldmatrix_x4_trans(r0, r1, r2, r3, addr);
                vt[jd2 * 2][0] = r0; vt[jd2 * 2][1] = r1;
                vt[jd2 * 2 + 1][0] = r2; vt[jd2 * 2 + 1][1] = r3;
            }
#pragma unroll
            for (int jd = 0; jd < 8; jd++)
                mma_f16(oacc[jd], ph[0], ph[1], ph[2], ph[3], vt[jd][0], vt[jd][1]);
#pragma unroll
            for (int jd = 0; jd < 8; jd++)
                mma_f16(oacc[jd], pl[0], pl[1], pl[2], pl[3], vt[jd][0], vt[jd][1]);
        }
    }

    // ---- epilogue: O/l -> g_Oc split rows [hi|lo|hi]
    const int bq = bh >> 4;
    const int h  = bh & 15;
    float inv0 = 1.0f / lr0, inv1 = 1.0f / lr1;
#pragma unroll
    for (int e = 0; e < 2; e++) {
        int trow = t0 + wid * 16 + g + e * 8;
        float inv = e ? inv1 : inv0;
        size_t rowbase = (size_t)(bq * SEQ + trow) * K3 + h * DHEAD;
#pragma unroll
        for (int jd = 0; jd < 8; jd++) {
            int d = jd * 8 + tq * 2;
            float v0 = oacc[jd][e * 2 + 0] * inv;
            float v1 = oacc[jd][e * 2 + 1] * inv;
            __nv_bfloat16 h0 = __float2bfloat16(v0), h1 = __float2bfloat16(v1);
            __nv_bfloat16 l0 = __float2bfloat16(v0 - __bfloat162float(h0));
            __nv_bfloat16 l1 = __float2bfloat16(v1 - __bfloat162float(h1));
            __nv_bfloat162 hh = __halves2bfloat162(h0, h1);
            __nv_bfloat162 ll = __halves2bfloat162(l0, l1);
            *reinterpret_cast<__nv_bfloat162*>(g_Oc + rowbase + d)        = hh;
            *reinterpret_cast<__nv_bfloat162*>(g_Oc + rowbase + 1024 + d) = ll;
            *reinterpret_cast<__nv_bfloat162*>(g_Oc + rowbase + 2048 + d) = hh;
        }
    }
}

// ---------------------------------------------------------------------------
extern "C" void kernel_launch(void* const* d_in, const int* in_sizes, int n_in,
                              void* d_out, int out_size) {
    const float* q   = (const float*)d_in[0];
    const float* kv  = (const float*)d_in[1];
    const float* Wq  = (const float*)d_in[2];
    const float* Wkv = (const float*)d_in[3];
    const float* W0  = (const float*)d_in[4];
    float* out = (float*)d_out;
    (void)in_sizes; (void)n_in; (void)out_size;

    (void)cudaFuncSetAttribute(attn_mma, cudaFuncAttributeMaxDynamicSharedMemorySize, ATTN_SMEM);
    (void)cudaFuncSetAttribute(gemm_mma<0>, cudaFuncAttributeMaxDynamicSharedMemorySize, GEMM_SMEM);
    (void)cudaFuncSetAttribute(gemm_mma<1>, cudaFuncAttributeMaxDynamicSharedMemorySize, GEMM_SMEM);
    (void)cudaFuncSetAttribute(gemm_mma<2>, cudaFuncAttributeMaxDynamicSharedMemorySize, GEMM_SMEM);

    split3<0><<<(MROWS * 512 + 255) / 256, 256>>>(q,   MROWS * 512);
    split3<1><<<(MROWS * 512 + 255) / 256, 256>>>(kv,  MROWS * 512);
    split3<2><<<(1024 * 512 + 255) / 256, 256>>>(Wq,  1024 * 512);
    split3<3><<<(2048 * 512 + 255) / 256, 256>>>(Wkv, 2048 * 512);
    split3<4><<<(1024 * 512 + 255) / 256, 256>>>(W0,  1024 * 512);

    gemm_mma<0><<<dim3(EDIM / 128, MROWS / 128), 256, GEMM_SMEM>>>(nullptr);
    gemm_mma<1><<<dim3(2 * EDIM / 128, MROWS / 128), 256, GEMM_SMEM>>>(nullptr);
    attn_mma<<<dim3(SEQ / 128, BATCH * HEADS), 256, ATTN_SMEM>>>();
    gemm_mma<2><<<dim3(DMODEL / 128, MROWS / 128), 256, GEMM_SMEM>>>(out);
}

// round 12
// speedup vs baseline: 1.4343x; 1.1926x over previous
#include <cuda_runtime.h>
#include <cuda_bf16.h>
#include <cuda_fp16.h>
#include <cstdint>

// Problem constants
#define BATCH   4
#define SEQ     2048
#define DMODEL  1024
#define HEADS   16
#define DHEAD   64
#define EDIM    1024
#define MROWS   (BATCH * SEQ)     // 8192
#define KDIM    1024

// ---------------------------------------------------------------------------
// Scratch (device globals; no allocation allowed)
// ---------------------------------------------------------------------------
// Attention operands (fp16). Q pre-scaled by 0.125 split hi/lo; K/V plain.
__device__ __align__(256) __half g_Qh[(size_t)BATCH * HEADS * SEQ * DHEAD];
__device__ __align__(256) __half g_Ql[(size_t)BATCH * HEADS * SEQ * DHEAD];
__device__ __align__(256) __half g_K [(size_t)BATCH * HEADS * SEQ * DHEAD];
__device__ __align__(256) __half g_V [(size_t)BATCH * HEADS * SEQ * DHEAD];
// GEMM activations: fp16 hi/lo pairs, [rows, 1024]
__device__ __align__(256) __half g_q_hi [(size_t)MROWS * KDIM];
__device__ __align__(256) __half g_q_lo [(size_t)MROWS * KDIM];
__device__ __align__(256) __half g_kv_hi[(size_t)MROWS * KDIM];
__device__ __align__(256) __half g_kv_lo[(size_t)MROWS * KDIM];
__device__ __align__(256) __half g_O_hi [(size_t)MROWS * KDIM];
__device__ __align__(256) __half g_O_lo [(size_t)MROWS * KDIM];
// GEMM weights: plain fp16, [N, 1024]
__device__ __align__(256) __half g_Wq16 [(size_t)1024 * KDIM];
__device__ __align__(256) __half g_Wkv16[(size_t)2048 * KDIM];
__device__ __align__(256) __half g_W016 [(size_t)1024 * KDIM];

// ---------------------------------------------------------------------------
// Helpers
// ---------------------------------------------------------------------------
__device__ __forceinline__ uint32_t smem_u32(const void* p) {
    uint32_t a;
    asm("{ .reg .u64 t; cvta.to.shared.u64 t, %1; cvt.u32.u64 %0, t; }" : "=r"(a) : "l"(p));
    return a;
}
__device__ __forceinline__ void cp_async16(uint32_t smem_addr, const void* gptr) {
    asm volatile("cp.async.cg.shared.global [%0], [%1], 16;" :: "r"(smem_addr), "l"(gptr));
}
#define CP_COMMIT() asm volatile("cp.async.commit_group;" ::: "memory")
#define CP_WAIT(n)  asm volatile("cp.async.wait_group %0;" :: "n"(n) : "memory")

__device__ __forceinline__ void ldmatrix_x4(uint32_t& r0, uint32_t& r1, uint32_t& r2,
                                            uint32_t& r3, uint32_t addr) {
    asm volatile("ldmatrix.sync.aligned.m8n8.x4.shared.b16 {%0,%1,%2,%3}, [%4];"
                 : "=r"(r0), "=r"(r1), "=r"(r2), "=r"(r3) : "r"(addr));
}
__device__ __forceinline__ void ldmatrix_x4_trans(uint32_t& r0, uint32_t& r1, uint32_t& r2,
                                                  uint32_t& r3, uint32_t addr) {
    asm volatile("ldmatrix.sync.aligned.m8n8.x4.trans.shared.b16 {%0,%1,%2,%3}, [%4];"
                 : "=r"(r0), "=r"(r1), "=r"(r2), "=r"(r3) : "r"(addr));
}
__device__ __forceinline__ void mma_f16(float* c,
                                        uint32_t a0, uint32_t a1, uint32_t a2, uint32_t a3,
                                        uint32_t b0, uint32_t b1) {
    asm volatile(
        "mma.sync.aligned.m16n8k16.row.col.f32.f16.f16.f32 "
        "{%0,%1,%2,%3}, {%4,%5,%6,%7}, {%8,%9}, {%0,%1,%2,%3};"
        : "+f"(c[0]), "+f"(c[1]), "+f"(c[2]), "+f"(c[3])
        : "r"(a0), "r"(a1), "r"(a2), "r"(a3), "r"(b0), "r"(b1));
}
__device__ __forceinline__ uint32_t pack_h2(float x, float y) {
    __half2 t = __halves2half2(__float2half(x), __float2half(y));
    return *reinterpret_cast<uint32_t*>(&t);
}

// ---------------------------------------------------------------------------
// split2: fp32 [R,1024] -> fp16 hi + lo arrays.  0: q, 1: kv
// cvt16:  fp32 [R,1024] -> plain fp16.           0: Wq, 1: Wkv, 2: W0
// ---------------------------------------------------------------------------
template <int WHICH>
__global__ void split2(const float* __restrict__ src, int total2) {
    __half* dh = (WHICH == 0) ? g_q_hi : g_kv_hi;
    __half* dl = (WHICH == 0) ? g_q_lo : g_kv_lo;
    int idx = blockIdx.x * blockDim.x + threadIdx.x;
    if (idx >= total2) return;
    float2 v = *reinterpret_cast<const float2*>(src + (size_t)idx * 2);
    __half h0 = __float2half(v.x), h1 = __float2half(v.y);
    __half l0 = __float2half(v.x - __half2float(h0));
    __half l1 = __float2half(v.y - __half2float(h1));
    *reinterpret_cast<__half2*>(dh + (size_t)idx * 2) = __halves2half2(h0, h1);
    *reinterpret_cast<__half2*>(dl + (size_t)idx * 2) = __halves2half2(l0, l1);
}
template <int WHICH>
__global__ void cvt16(const float* __restrict__ src, int total2) {
    __half* dst = (WHICH == 0) ? g_Wq16 : (WHICH == 1) ? g_Wkv16 : g_W016;
    int idx = blockIdx.x * blockDim.x + threadIdx.x;
    if (idx >= total2) return;
    float2 v = *reinterpret_cast<const float2*>(src + (size_t)idx * 2);
    *reinterpret_cast<__half2*>(dst + (size_t)idx * 2) =
        __halves2half2(__float2half(v.x), __float2half(v.y));
}

// ---------------------------------------------------------------------------
// fp16 2-product TN GEMM: C = (Ah + Al) . W^T, K=1024, tile 128x128, BK=64.
// Stage = [Ah | Al | W] tiles; 3-stage ring, ONE barrier per chunk.
// W fragments loaded once, used by both products.
// MODE 0: A=q,  W=Wq,  scatter n=(d*16+h)       -> g_Qh/g_Ql (x0.125)
// MODE 1: A=kv, W=Wkv, scatter n=(d*32+kk*16+h) -> g_K / g_V
// MODE 2: A=O,  W=W0,  C[m*1024+n] = v (d_out)
// ---------------------------------------------------------------------------
#define GNCH        (KDIM / 64)          // 16
#define ROWB        144                  // 64 fp16 = 128B data + 16B pad
#define TILE_B      (128 * ROWB)         // 18432
#define STAGE_B     (3 * TILE_B)         // 55296
#define GEMM_SMEM   (3 * STAGE_B)        // 165888

template <int MODE>
__global__ __launch_bounds__(256) void gemm_mma(float* __restrict__ C) {
    extern __shared__ char smem[];
    const uint32_t sb = smem_u32(smem);
    const int tid = threadIdx.x, wid = tid >> 5, lane = tid & 31;
    const int wm = wid >> 2, wn = wid & 3;
    const int m0 = blockIdx.y * 128, n0 = blockIdx.x * 128;

    const __half* Ah = (MODE == 0) ? g_q_hi : (MODE == 1) ? g_kv_hi : g_O_hi;
    const __half* Al = (MODE == 0) ? g_q_lo : (MODE == 1) ? g_kv_lo : g_O_lo;
    const __half* Wg = (MODE == 0) ? g_Wq16 : (MODE == 1) ? g_Wkv16 : g_W016;
    Ah += (size_t)m0 * KDIM;
    Al += (size_t)m0 * KDIM;
    Wg += (size_t)n0 * KDIM;

    float acc[4][4][4];
#pragma unroll
    for (int i = 0; i < 4; i++)
#pragma unroll
        for (int j = 0; j < 4; j++)
#pragma unroll
            for (int e = 0; e < 4; e++) acc[i][j][e] = 0.0f;

    auto load_stage = [&](int ch, int s) {
        uint32_t base = sb + s * STAGE_B;
#pragma unroll
        for (int t = 0; t < 12; t++) {
            int idx = tid + t * 256;            // 0..3071
            int mat = idx >> 10;                // 0=Ah,1=Al,2=W
            int rem = idx & 1023;
            int row = rem >> 3, ck = rem & 7;
            const __half* src = (mat == 0) ? Ah : (mat == 1) ? Al : Wg;
            cp_async16(base + mat * TILE_B + row * ROWB + ck * 16,
                       src + (size_t)row * KDIM + ch * 64 + ck * 8);
        }
        CP_COMMIT();
    };

    load_stage(0, 0);
    load_stage(1, 1);

    const uint32_t a_row = (uint32_t)(wm * 64 + (lane & 15));
    const uint32_t a_kb  = (uint32_t)(((lane >> 4) & 1) * 16);
    const uint32_t b_row = (uint32_t)(wn * 32 + (lane & 7) + ((lane >> 4) & 1) * 8);
    const uint32_t b_kb  = (uint32_t)(((lane >> 3) & 1) * 16);

    for (int ch = 0; ch < GNCH; ch++) {
        if (ch + 1 < GNCH) { CP_WAIT(1); } else { CP_WAIT(0); }
        __syncthreads();
        if (ch + 2 < GNCH) load_stage(ch + 2, (ch + 2) % 3);

        uint32_t hBase = sb + (ch % 3) * STAGE_B;
        uint32_t lBase = hBase + TILE_B;
        uint32_t wBase = hBase + 2 * TILE_B;
#pragma unroll
        for (int ks = 0; ks < 4; ks++) {
            uint32_t ah[4][4], al[4][4], b[4][2];
#pragma unroll
            for (int i = 0; i < 4; i++) {
                uint32_t off = (a_row + i * 16) * ROWB + ks * 32 + a_kb;
                ldmatrix_x4(ah[i][0], ah[i][1], ah[i][2], ah[i][3], hBase + off);
                ldmatrix_x4(al[i][0], al[i][1], al[i][2], al[i][3], lBase + off);
            }
#pragma unroll
            for (int j2 = 0; j2 < 2; j2++) {
                uint32_t r0, r1, r2, r3;
                uint32_t addr = wBase + (b_row + j2 * 16) * ROWB + ks * 32 + b_kb;
                ldmatrix_x4(r0, r1, r2, r3, addr);
                b[j2 * 2][0] = r0; b[j2 * 2][1] = r1;
                b[j2 * 2 + 1][0] = r2; b[j2 * 2 + 1][1] = r3;
            }
#pragma unroll
            for (int i = 0; i < 4; i++)
#pragma unroll
                for (int j = 0; j < 4; j++)
                    mma_f16(acc[i][j], ah[i][0], ah[i][1], ah[i][2], ah[i][3],
                            b[j][0], b[j][1]);
#pragma unroll
            for (int i = 0; i < 4; i++)
#pragma unroll
                for (int j = 0; j < 4; j++)
                    mma_f16(acc[i][j], al[i][0], al[i][1], al[i][2], al[i][3],
                            b[j][0], b[j][1]);
        }
    }

    const int g = lane >> 2, tq = lane & 3;
#pragma unroll
    for (int i = 0; i < 4; i++) {
#pragma unroll
        for (int e = 0; e < 2; e++) {
            int m = m0 + wm * 64 + i * 16 + g + e * 8;
            int b = m >> 11;
            int t = m & 2047;
#pragma unroll
            for (int j = 0; j < 4; j++) {
#pragma unroll
                for (int x = 0; x < 2; x++) {
                    int n = n0 + wn * 32 + j * 8 + tq * 2 + x;
                    float v = acc[i][j][e * 2 + x];
                    if (MODE == 0) {
                        int d = n >> 4, h = n & 15;
                        size_t a5 = ((((size_t)b * HEADS + h) * SEQ + t) << 6) + d;
                        float vs = v * 0.125f;
                        __half hi = __float2half(vs);
                        g_Qh[a5] = hi;
                        g_Ql[a5] = __float2half(vs - __half2float(hi));
                    } else if (MODE == 1) {
                        int h = n & 15, kk = (n >> 4) & 1, d = n >> 5;
                        size_t a5 = ((((size_t)b * HEADS + h) * SEQ + t) << 6) + d;
                        if (kk) g_V[a5] = __float2half(v);
                        else    g_K[a5] = __float2half(v);
                    } else {
                        C[(size_t)m * 1024 + n] = v;
                    }
                }
            }
        }
    }
}

// ---------------------------------------------------------------------------
// Flash attention, fp16 2-product asymmetric split (unchanged from R11):
//   S = (Qh + Ql) . K ;  O = (Ph + Pl) . V
// CTA: 128 q-rows, 8 warps, key tiles of 64; 3-stage KV ring, one barrier/tile.
// Epilogue writes O as fp16 hi/lo rows for the out-projection.
// ---------------------------------------------------------------------------
#define AROWB    144
#define ATILE_B  (64 * AROWB)            // 9216
#define ASTAGE_B (2 * ATILE_B)           // 18432  (K | V)
#define ATTN_SMEM (3 * ASTAGE_B)         // 55296

__global__ __launch_bounds__(256) void attn_mma() {
    extern __shared__ char smem[];
    const uint32_t sb = smem_u32(smem);
    const int tid = threadIdx.x, wid = tid >> 5, lane = tid & 31;
    const int g = lane >> 2, tq = lane & 3;
    const int bh = blockIdx.y;
    const int t0 = blockIdx.x << 7;

    const size_t bhoff = (size_t)bh * SEQ * DHEAD;
    const __half* Qh = g_Qh + bhoff + (size_t)t0 * DHEAD;
    const __half* Ql = g_Ql + bhoff + (size_t)t0 * DHEAD;
    const __half* Kg = g_K + bhoff;
    const __half* Vg = g_V + bhoff;

    // ---- Stage Q (hi at 0, lo at +2*ATILE_B) and extract fragments
#pragma unroll
    for (int t = 0; t < 8; t++) {
        int idx = tid + t * 256;             // 0..2047
        int mat = idx >> 10;                 // 0=hi,1=lo
        int r   = (idx >> 3) & 127;
        int ck  = idx & 7;
        const __half* src = mat ? Ql : Qh;
        cp_async16(sb + mat * (2 * ATILE_B) + r * AROWB + ck * 16,
                   src + (size_t)r * DHEAD + ck * 8);
    }
    CP_COMMIT();
    CP_WAIT(0);
    __syncthreads();

    uint32_t qh[4][4], ql[4][4];
    {
        uint32_t qrow = (uint32_t)(wid * 16 + (lane & 15));
        uint32_t kb   = (uint32_t)(((lane >> 4) & 1) * 16);
#pragma unroll
        for (int ks = 0; ks < 4; ks++) {
            uint32_t addr = sb + qrow * AROWB + ks * 32 + kb;
            ldmatrix_x4(qh[ks][0], qh[ks][1], qh[ks][2], qh[ks][3], addr);
            ldmatrix_x4(ql[ks][0], ql[ks][1], ql[ks][2], ql[ks][3],
                        addr + 2 * ATILE_B);
        }
    }
    __syncthreads();

    auto load_kv = [&](int jt, int s) {
        uint32_t base = sb + s * ASTAGE_B;
#pragma unroll
        for (int t = 0; t < 4; t++) {
            int idx = tid + t * 256;         // 0..1023
            int mat = idx >> 9;              // 0=K,1=V
            int r   = (idx >> 3) & 63;
            int ck  = idx & 7;
            const __half* src = mat ? Vg : Kg;
            cp_async16(base + mat * ATILE_B + r * AROWB + ck * 16,
                       src + (size_t)(jt * 64 + r) * DHEAD + ck * 8);
        }
        CP_COMMIT();
    };

    load_kv(0, 0);
    load_kv(1, 1);

    float oacc[8][4];
#pragma unroll
    for (int j = 0; j < 8; j++)
#pragma unroll
        for (int e = 0; e < 4; e++) oacc[j][e] = 0.0f;
    float mr0 = -1e30f, mr1 = -1e30f, lr0 = 0.0f, lr1 = 0.0f;

    const uint32_t kb_row = (uint32_t)((lane & 7) + ((lane >> 4) & 1) * 8);
    const uint32_t kb_kb  = (uint32_t)(((lane >> 3) & 1) * 16);
    const uint32_t v_row  = (uint32_t)((lane & 7) + ((lane >> 3) & 1) * 8);
    const uint32_t v_cb   = (uint32_t)(((lane >> 4) & 1) * 8 * 2);

    for (int jt = 0; jt < SEQ / 64; jt++) {
        if (jt + 1 < SEQ / 64) { CP_WAIT(1); } else { CP_WAIT(0); }
        __syncthreads();
        if (jt + 2 < SEQ / 64) load_kv(jt + 2, (jt + 2) % 3);
        uint32_t st = sb + (jt % 3) * ASTAGE_B;

        // ---- S = Qh*K + Ql*K
        float sacc[8][4];
#pragma unroll
        for (int j = 0; j < 8; j++)
#pragma unroll
            for (int e = 0; e < 4; e++) sacc[j][e] = 0.0f;
#pragma unroll
        for (int ks = 0; ks < 4; ks++) {
            uint32_t bt[8][2];
#pragma unroll
            for (int j2 = 0; j2 < 4; j2++) {
                uint32_t r0, r1, r2, r3;
                uint32_t addr = st + (kb_row + j2 * 16) * AROWB + ks * 32 + kb_kb;
                ldmatrix_x4(r0, r1, r2, r3, addr);
                bt[j2 * 2][0] = r0; bt[j2 * 2][1] = r1;
                bt[j2 * 2 + 1][0] = r2; bt[j2 * 2 + 1][1] = r3;
            }
#pragma unroll
            for (int j = 0; j < 8; j++)
                mma_f16(sacc[j], qh[ks][0], qh[ks][1], qh[ks][2], qh[ks][3],
                        bt[j][0], bt[j][1]);
#pragma unroll
            for (int j = 0; j < 8; j++)
                mma_f16(sacc[j], ql[ks][0], ql[ks][1], ql[ks][2], ql[ks][3],
                        bt[j][0], bt[j][1]);
        }

        // ---- online softmax
        float mx0 = -1e30f, mx1 = -1e30f;
#pragma unroll
        for (int j = 0; j < 8; j++) {
            mx0 = fmaxf(mx0, fmaxf(sacc[j][0], sacc[j][1]));
            mx1 = fmaxf(mx1, fmaxf(sacc[j][2], sacc[j][3]));
        }
        mx0 = fmaxf(mx0, __shfl_xor_sync(0xffffffffu, mx0, 1));
        mx0 = fmaxf(mx0, __shfl_xor_sync(0xffffffffu, mx0, 2));
        mx1 = fmaxf(mx1, __shfl_xor_sync(0xffffffffu, mx1, 1));
        mx1 = fmaxf(mx1, __shfl_xor_sync(0xffffffffu, mx1, 2));
        float mn0 = fmaxf(mr0, mx0), mn1 = fmaxf(mr1, mx1);
        float al0 = __expf(mr0 - mn0), al1 = __expf(mr1 - mn1);
        mr0 = mn0; mr1 = mn1;
        float sum0 = 0.0f, sum1 = 0.0f;
#pragma unroll
        for (int j = 0; j < 8; j++) {
            sacc[j][0] = __expf(sacc[j][0] - mn0);
            sacc[j][1] = __expf(sacc[j][1] - mn0);
            sacc[j][2] = __expf(sacc[j][2] - mn1);
            sacc[j][3] = __expf(sacc[j][3] - mn1);
            sum0 += sacc[j][0] + sacc[j][1];
            sum1 += sacc[j][2] + sacc[j][3];
        }
        sum0 += __shfl_xor_sync(0xffffffffu, sum0, 1);
        sum0 += __shfl_xor_sync(0xffffffffu, sum0, 2);
        sum1 += __shfl_xor_sync(0xffffffffu, sum1, 1);
        sum1 += __shfl_xor_sync(0xffffffffu, sum1, 2);
        lr0 = lr0 * al0 + sum0;
        lr1 = lr1 * al1 + sum1;
#pragma unroll
        for (int j = 0; j < 8; j++) {
            oacc[j][0] *= al0; oacc[j][1] *= al0;
            oacc[j][2] *= al1; oacc[j][3] *= al1;
        }

        // ---- O += Ph*V + Pl*V
#pragma unroll
        for (int cs = 0; cs < 4; cs++) {
            int j0 = cs * 2, j1 = cs * 2 + 1;
            uint32_t ph[4], pl[4];
            {
                float p00 = sacc[j0][0], p01 = sacc[j0][1];
                float p02 = sacc[j0][2], p03 = sacc[j0][3];
                float p10 = sacc[j1][0], p11 = sacc[j1][1];
                float p12 = sacc[j1][2], p13 = sacc[j1][3];
                ph[0] = pack_h2(p00, p01);
                ph[1] = pack_h2(p02, p03);
                ph[2] = pack_h2(p10, p11);
                ph[3] = pack_h2(p12, p13);
                __half2 h;
                h = *reinterpret_cast<__half2*>(&ph[0]);
                pl[0] = pack_h2(p00 - __half2float(h.x), p01 - __half2float(h.y));
                h = *reinterpret_cast<__half2*>(&ph[1]);
                pl[1] = pack_h2(p02 - __half2float(h.x), p03 - __half2float(h.y));
                h = *reinterpret_cast<__half2*>(&ph[2]);
                pl[2] = pack_h2(p10 - __half2float(h.x), p11 - __half2float(h.y));
                h = *reinterpret_cast<__half2*>(&ph[3]);
                pl[3] = pack_h2(p12 - __half2float(h.x), p13 - __half2float(h.y));
            }
            uint32_t vt[8][2];
#pragma unroll
            for (int jd2 = 0; jd2 < 4; jd2++) {
                uint32_t r0, r1, r2, r3;
                uint32_t addr = st + ATILE_B + (cs * 16 + v_row) * AROWB
                              + jd2 * 32 + v_cb;
                ldmatrix_x4_trans(r0, r1, r2, r3, addr);
                vt[jd2 * 2][0] = r0; vt[jd2 * 2][1] = r1;
                vt[jd2 * 2 + 1][0] = r2; vt[jd2 * 2 + 1][1] = r3;
            }
#pragma unroll
            for (int jd = 0; jd < 8; jd++)
                mma_f16(oacc[jd], ph[0], ph[1], ph[2], ph[3], vt[jd][0], vt[jd][1]);
#pragma unroll
            for (int jd = 0; jd < 8; jd++)
                mma_f16(oacc[jd], pl[0], pl[1], pl[2], pl[3], vt[jd][0], vt[jd][1]);
        }
    }

    // ---- epilogue: O/l -> g_O_hi / g_O_lo fp16 rows
    const int bq = bh >> 4;
    const int h  = bh & 15;
    float inv0 = 1.0f / lr0, inv1 = 1.0f / lr1;
#pragma unroll
    for (int e = 0; e < 2; e++) {
        int trow = t0 + wid * 16 + g + e * 8;
        float inv = e ? inv1 : inv0;
        size_t rowbase = (size_t)(bq * SEQ + trow) * KDIM + h * DHEAD;
#pragma unroll
        for (int jd = 0; jd < 8; jd++) {
            int d = jd * 8 + tq * 2;
            float v0 = oacc[jd][e * 2 + 0] * inv;
            float v1 = oacc[jd][e * 2 + 1] * inv;
            __half h0 = __float2half(v0), h1 = __float2half(v1);
            __half l0 = __float2half(v0 - __half2float(h0));
            __half l1 = __float2half(v1 - __half2float(h1));
            *reinterpret_cast<__half2*>(g_O_hi + rowbase + d) = __halves2half2(h0, h1);
            *reinterpret_cast<__half2*>(g_O_lo + rowbase + d) = __halves2half2(l0, l1);
        }
    }
}

// ---------------------------------------------------------------------------
extern "C" void kernel_launch(void* const* d_in, const int* in_sizes, int n_in,
                              void* d_out, int out_size) {
    const float* q   = (const float*)d_in[0];
    const float* kv  = (const float*)d_in[1];
    const float* Wq  = (const float*)d_in[2];
    const float* Wkv = (const float*)d_in[3];
    const float* W0  = (const float*)d_in[4];
    float* out = (float*)d_out;
    (void)in_sizes; (void)n_in; (void)out_size;

    (void)cudaFuncSetAttribute(attn_mma, cudaFuncAttributeMaxDynamicSharedMemorySize, ATTN_SMEM);
    (void)cudaFuncSetAttribute(gemm_mma<0>, cudaFuncAttributeMaxDynamicSharedMemorySize, GEMM_SMEM);
    (void)cudaFuncSetAttribute(gemm_mma<1>, cudaFuncAttributeMaxDynamicSharedMemorySize, GEMM_SMEM);
    (void)cudaFuncSetAttribute(gemm_mma<2>, cudaFuncAttributeMaxDynamicSharedMemorySize, GEMM_SMEM);

    // Conversions
    split2<0><<<(MROWS * 512 + 255) / 256, 256>>>(q,  MROWS * 512);
    split2<1><<<(MROWS * 512 + 255) / 256, 256>>>(kv, MROWS * 512);
    cvt16<0><<<(1024 * 512 + 255) / 256, 256>>>(Wq,  1024 * 512);
    cvt16<1><<<(2048 * 512 + 255) / 256, 256>>>(Wkv, 2048 * 512);
    cvt16<2><<<(1024 * 512 + 255) / 256, 256>>>(W0,  1024 * 512);

    // Projections (fp16 2-product)
    gemm_mma<0><<<dim3(EDIM / 128, MROWS / 128), 256, GEMM_SMEM>>>(nullptr);
    gemm_mma<1><<<dim3(2 * EDIM / 128, MROWS / 128), 256, GEMM_SMEM>>>(nullptr);
    // Attention (fp16 2-product)
    attn_mma<<<dim3(SEQ / 128, BATCH * HEADS), 256, ATTN_SMEM>>>();
    // Output projection
    gemm_mma<2><<<dim3(DMODEL / 128, MROWS / 128), 256, GEMM_SMEM>>>(out);
}

// round 13
// speedup vs baseline: 1.6366x; 1.1410x over previous
#include <cuda_runtime.h>
#include <cuda_bf16.h>
#include <cuda_fp16.h>
#include <cstdint>

// Problem constants
#define BATCH   4
#define SEQ     2048
#define DMODEL  1024
#define HEADS   16
#define DHEAD   64
#define EDIM    1024
#define MROWS   (BATCH * SEQ)     // 8192
#define KDIM    1024
#define QSCALE  (0.125f * 1.44269504088896340736f)   // 1/sqrt(64) * log2(e)

// ---------------------------------------------------------------------------
// Scratch (device globals; no allocation allowed)
// ---------------------------------------------------------------------------
__device__ __align__(256) __half g_Qh[(size_t)BATCH * HEADS * SEQ * DHEAD];
__device__ __align__(256) __half g_Ql[(size_t)BATCH * HEADS * SEQ * DHEAD];
__device__ __align__(256) __half g_K [(size_t)BATCH * HEADS * SEQ * DHEAD];
__device__ __align__(256) __half g_V [(size_t)BATCH * HEADS * SEQ * DHEAD];
__device__ __align__(256) __half g_q_hi [(size_t)MROWS * KDIM];
__device__ __align__(256) __half g_q_lo [(size_t)MROWS * KDIM];
__device__ __align__(256) __half g_kv_hi[(size_t)MROWS * KDIM];
__device__ __align__(256) __half g_kv_lo[(size_t)MROWS * KDIM];
__device__ __align__(256) __half g_O_hi [(size_t)MROWS * KDIM];
__device__ __align__(256) __half g_O_lo [(size_t)MROWS * KDIM];
__device__ __align__(256) __half g_Wq16 [(size_t)1024 * KDIM];
__device__ __align__(256) __half g_Wkv16[(size_t)2048 * KDIM];
__device__ __align__(256) __half g_W016 [(size_t)1024 * KDIM];

// ---------------------------------------------------------------------------
// Helpers
// ---------------------------------------------------------------------------
__device__ __forceinline__ uint32_t smem_u32(const void* p) {
    uint32_t a;
    asm("{ .reg .u64 t; cvta.to.shared.u64 t, %1; cvt.u32.u64 %0, t; }" : "=r"(a) : "l"(p));
    return a;
}
__device__ __forceinline__ void cp_async16(uint32_t smem_addr, const void* gptr) {
    asm volatile("cp.async.cg.shared.global [%0], [%1], 16;" :: "r"(smem_addr), "l"(gptr));
}
#define CP_COMMIT() asm volatile("cp.async.commit_group;" ::: "memory")
#define CP_WAIT(n)  asm volatile("cp.async.wait_group %0;" :: "n"(n) : "memory")

__device__ __forceinline__ void ldmatrix_x4(uint32_t& r0, uint32_t& r1, uint32_t& r2,
                                            uint32_t& r3, uint32_t addr) {
    asm volatile("ldmatrix.sync.aligned.m8n8.x4.shared.b16 {%0,%1,%2,%3}, [%4];"
                 : "=r"(r0), "=r"(r1), "=r"(r2), "=r"(r3) : "r"(addr));
}
__device__ __forceinline__ void ldmatrix_x4_trans(uint32_t& r0, uint32_t& r1, uint32_t& r2,
                                                  uint32_t& r3, uint32_t addr) {
    asm volatile("ldmatrix.sync.aligned.m8n8.x4.trans.shared.b16 {%0,%1,%2,%3}, [%4];"
                 : "=r"(r0), "=r"(r1), "=r"(r2), "=r"(r3) : "r"(addr));
}
__device__ __forceinline__ void mma_f16(float* c,
                                        uint32_t a0, uint32_t a1, uint32_t a2, uint32_t a3,
                                        uint32_t b0, uint32_t b1) {
    asm volatile(
        "mma.sync.aligned.m16n8k16.row.col.f32.f16.f16.f32 "
        "{%0,%1,%2,%3}, {%4,%5,%6,%7}, {%8,%9}, {%0,%1,%2,%3};"
        : "+f"(c[0]), "+f"(c[1]), "+f"(c[2]), "+f"(c[3])
        : "r"(a0), "r"(a1), "r"(a2), "r"(a3), "r"(b0), "r"(b1));
}
__device__ __forceinline__ uint32_t pack_h2(float x, float y) {
    __half2 t = __halves2half2(__float2half(x), __float2half(y));
    return *reinterpret_cast<uint32_t*>(&t);
}
__device__ __forceinline__ uint32_t ex2_f16x2(uint32_t x) {
    uint32_t r;
    asm volatile("ex2.approx.f16x2 %0, %1;" : "=r"(r) : "r"(x));
    return r;
}

// ---------------------------------------------------------------------------
// split2: fp32 [R,1024] -> fp16 hi + lo arrays.  0: q, 1: kv
// cvt16:  fp32 [R,1024] -> plain fp16.           0: Wq, 1: Wkv, 2: W0
// ---------------------------------------------------------------------------
template <int WHICH>
__global__ void split2(const float* __restrict__ src, int total2) {
    __half* dh = (WHICH == 0) ? g_q_hi : g_kv_hi;
    __half* dl = (WHICH == 0) ? g_q_lo : g_kv_lo;
    int idx = blockIdx.x * blockDim.x + threadIdx.x;
    if (idx >= total2) return;
    float2 v = *reinterpret_cast<const float2*>(src + (size_t)idx * 2);
    __half h0 = __float2half(v.x), h1 = __float2half(v.y);
    __half l0 = __float2half(v.x - __half2float(h0));
    __half l1 = __float2half(v.y - __half2float(h1));
    *reinterpret_cast<__half2*>(dh + (size_t)idx * 2) = __halves2half2(h0, h1);
    *reinterpret_cast<__half2*>(dl + (size_t)idx * 2) = __halves2half2(l0, l1);
}
template <int WHICH>
__global__ void cvt16(const float* __restrict__ src, int total2) {
    __half* dst = (WHICH == 0) ? g_Wq16 : (WHICH == 1) ? g_Wkv16 : g_W016;
    int idx = blockIdx.x * blockDim.x + threadIdx.x;
    if (idx >= total2) return;
    float2 v = *reinterpret_cast<const float2*>(src + (size_t)idx * 2);
    *reinterpret_cast<__half2*>(dst + (size_t)idx * 2) =
        __halves2half2(__float2half(v.x), __float2half(v.y));
}

// ---------------------------------------------------------------------------
// fp16 2-product TN GEMM: C = (Ah + Al) . W^T, K=1024, tile 128x128, BK=64.
// ---------------------------------------------------------------------------
#define GNCH        (KDIM / 64)          // 16
#define ROWB        144
#define TILE_B      (128 * ROWB)         // 18432
#define STAGE_B     (3 * TILE_B)         // 55296
#define GEMM_SMEM   (3 * STAGE_B)        // 165888

template <int MODE>
__global__ __launch_bounds__(256) void gemm_mma(float* __restrict__ C) {
    extern __shared__ char smem[];
    const uint32_t sb = smem_u32(smem);
    const int tid = threadIdx.x, wid = tid >> 5, lane = tid & 31;
    const int wm = wid >> 2, wn = wid & 3;
    const int m0 = blockIdx.y * 128, n0 = blockIdx.x * 128;

    const __half* Ah = (MODE == 0) ? g_q_hi : (MODE == 1) ? g_kv_hi : g_O_hi;
    const __half* Al = (MODE == 0) ? g_q_lo : (MODE == 1) ? g_kv_lo : g_O_lo;
    const __half* Wg = (MODE == 0) ? g_Wq16 : (MODE == 1) ? g_Wkv16 : g_W016;
    Ah += (size_t)m0 * KDIM;
    Al += (size_t)m0 * KDIM;
    Wg += (size_t)n0 * KDIM;

    float acc[4][4][4];
#pragma unroll
    for (int i = 0; i < 4; i++)
#pragma unroll
        for (int j = 0; j < 4; j++)
#pragma unroll
            for (int e = 0; e < 4; e++) acc[i][j][e] = 0.0f;

    auto load_stage = [&](int ch, int s) {
        uint32_t base = sb + s * STAGE_B;
#pragma unroll
        for (int t = 0; t < 12; t++) {
            int idx = tid + t * 256;
            int mat = idx >> 10;
            int rem = idx & 1023;
            int row = rem >> 3, ck = rem & 7;
            const __half* src = (mat == 0) ? Ah : (mat == 1) ? Al : Wg;
            cp_async16(base + mat * TILE_B + row * ROWB + ck * 16,
                       src + (size_t)row * KDIM + ch * 64 + ck * 8);
        }
        CP_COMMIT();
    };

    load_stage(0, 0);
    load_stage(1, 1);

    const uint32_t a_row = (uint32_t)(wm * 64 + (lane & 15));
    const uint32_t a_kb  = (uint32_t)(((lane >> 4) & 1) * 16);
    const uint32_t b_row = (uint32_t)(wn * 32 + (lane & 7) + ((lane >> 4) & 1) * 8);
    const uint32_t b_kb  = (uint32_t)(((lane >> 3) & 1) * 16);

    for (int ch = 0; ch < GNCH; ch++) {
        if (ch + 1 < GNCH) { CP_WAIT(1); } else { CP_WAIT(0); }
        __syncthreads();
        if (ch + 2 < GNCH) load_stage(ch + 2, (ch + 2) % 3);

        uint32_t hBase = sb + (ch % 3) * STAGE_B;
        uint32_t lBase = hBase + TILE_B;
        uint32_t wBase = hBase + 2 * TILE_B;
#pragma unroll
        for (int ks = 0; ks < 4; ks++) {
            uint32_t ah[4][4], al[4][4], b[4][2];
#pragma unroll
            for (int i = 0; i < 4; i++) {
                uint32_t off = (a_row + i * 16) * ROWB + ks * 32 + a_kb;
                ldmatrix_x4(ah[i][0], ah[i][1], ah[i][2], ah[i][3], hBase + off);
                ldmatrix_x4(al[i][0], al[i][1], al[i][2], al[i][3], lBase + off);
            }
#pragma unroll
            for (int j2 = 0; j2 < 2; j2++) {
                uint32_t r0, r1, r2, r3;
                uint32_t addr = wBase + (b_row + j2 * 16) * ROWB + ks * 32 + b_kb;
                ldmatrix_x4(r0, r1, r2, r3, addr);
                b[j2 * 2][0] = r0; b[j2 * 2][1] = r1;
                b[j2 * 2 + 1][0] = r2; b[j2 * 2 + 1][1] = r3;
            }
#pragma unroll
            for (int i = 0; i < 4; i++)
#pragma unroll
                for (int j = 0; j < 4; j++)
                    mma_f16(acc[i][j], ah[i][0], ah[i][1], ah[i][2], ah[i][3],
                            b[j][0], b[j][1]);
#pragma unroll
            for (int i = 0; i < 4; i++)
#pragma unroll
                for (int j = 0; j < 4; j++)
                    mma_f16(acc[i][j], al[i][0], al[i][1], al[i][2], al[i][3],
                            b[j][0], b[j][1]);
        }
    }

    const int g = lane >> 2, tq = lane & 3;
#pragma unroll
    for (int i = 0; i < 4; i++) {
#pragma unroll
        for (int e = 0; e < 2; e++) {
            int m = m0 + wm * 64 + i * 16 + g + e * 8;
            int b = m >> 11;
            int t = m & 2047;
#pragma unroll
            for (int j = 0; j < 4; j++) {
#pragma unroll
                for (int x = 0; x < 2; x++) {
                    int n = n0 + wn * 32 + j * 8 + tq * 2 + x;
                    float v = acc[i][j][e * 2 + x];
                    if (MODE == 0) {
                        int d = n >> 4, h = n & 15;
                        size_t a5 = ((((size_t)b * HEADS + h) * SEQ + t) << 6) + d;
                        float vs = v * QSCALE;          // includes log2(e)
                        __half hi = __float2half(vs);
                        g_Qh[a5] = hi;
                        g_Ql[a5] = __float2half(vs - __half2float(hi));
                    } else if (MODE == 1) {
                        int h = n & 15, kk = (n >> 4) & 1, d = n >> 5;
                        size_t a5 = ((((size_t)b * HEADS + h) * SEQ + t) << 6) + d;
                        if (kk) g_V[a5] = __float2half(v);
                        else    g_K[a5] = __float2half(v);
                    } else {
                        C[(size_t)m * 1024 + n] = v;
                    }
                }
            }
        }
    }
}

// ---------------------------------------------------------------------------
// Flash attention, fp16, log2-domain softmax with ex2.approx.f16x2:
//   S = (Qh + Ql) . K      (S in log2 units; Q pre-scaled by 0.125*log2e)
//   P = 2^(S - m)          (fp16 directly, via ex2.approx.f16x2)
//   O = P . V              (single product; P exact in fp16)
// ---------------------------------------------------------------------------
#define AROWB    144
#define ATILE_B  (64 * AROWB)            // 9216
#define ASTAGE_B (2 * ATILE_B)           // 18432  (K | V)
#define ATTN_SMEM (3 * ASTAGE_B)         // 55296

__global__ __launch_bounds__(256) void attn_mma() {
    extern __shared__ char smem[];
    const uint32_t sb = smem_u32(smem);
    const int tid = threadIdx.x, wid = tid >> 5, lane = tid & 31;
    const int g = lane >> 2, tq = lane & 3;
    const int bh = blockIdx.y;
    const int t0 = blockIdx.x << 7;

    const size_t bhoff = (size_t)bh * SEQ * DHEAD;
    const __half* Qh = g_Qh + bhoff + (size_t)t0 * DHEAD;
    const __half* Ql = g_Ql + bhoff + (size_t)t0 * DHEAD;
    const __half* Kg = g_K + bhoff;
    const __half* Vg = g_V + bhoff;

    // ---- Stage Q (hi at 0, lo at +2*ATILE_B) and extract fragments
#pragma unroll
    for (int t = 0; t < 8; t++) {
        int idx = tid + t * 256;
        int mat = idx >> 10;
        int r   = (idx >> 3) & 127;
        int ck  = idx & 7;
        const __half* src = mat ? Ql : Qh;
        cp_async16(sb + mat * (2 * ATILE_B) + r * AROWB + ck * 16,
                   src + (size_t)r * DHEAD + ck * 8);
    }
    CP_COMMIT();
    CP_WAIT(0);
    __syncthreads();

    uint32_t qh[4][4], ql[4][4];
    {
        uint32_t qrow = (uint32_t)(wid * 16 + (lane & 15));
        uint32_t kb   = (uint32_t)(((lane >> 4) & 1) * 16);
#pragma unroll
        for (int ks = 0; ks < 4; ks++) {
            uint32_t addr = sb + qrow * AROWB + ks * 32 + kb;
            ldmatrix_x4(qh[ks][0], qh[ks][1], qh[ks][2], qh[ks][3], addr);
            ldmatrix_x4(ql[ks][0], ql[ks][1], ql[ks][2], ql[ks][3],
                        addr + 2 * ATILE_B);
        }
    }
    __syncthreads();

    auto load_kv = [&](int jt, int s) {
        uint32_t base = sb + s * ASTAGE_B;
#pragma unroll
        for (int t = 0; t < 4; t++) {
            int idx = tid + t * 256;
            int mat = idx >> 9;
            int r   = (idx >> 3) & 63;
            int ck  = idx & 7;
            const __half* src = mat ? Vg : Kg;
            cp_async16(base + mat * ATILE_B + r * AROWB + ck * 16,
                       src + (size_t)(jt * 64 + r) * DHEAD + ck * 8);
        }
        CP_COMMIT();
    };

    load_kv(0, 0);
    load_kv(1, 1);

    float oacc[8][4];
#pragma unroll
    for (int j = 0; j < 8; j++)
#pragma unroll
        for (int e = 0; e < 4; e++) oacc[j][e] = 0.0f;
    float mr0 = -1e30f, mr1 = -1e30f, lr0 = 0.0f, lr1 = 0.0f;

    const uint32_t kb_row = (uint32_t)((lane & 7) + ((lane >> 4) & 1) * 8);
    const uint32_t kb_kb  = (uint32_t)(((lane >> 3) & 1) * 16);
    const uint32_t v_row  = (uint32_t)((lane & 7) + ((lane >> 3) & 1) * 8);
    const uint32_t v_cb   = (uint32_t)(((lane >> 4) & 1) * 8 * 2);

    for (int jt = 0; jt < SEQ / 64; jt++) {
        if (jt + 1 < SEQ / 64) { CP_WAIT(1); } else { CP_WAIT(0); }
        __syncthreads();
        if (jt + 2 < SEQ / 64) load_kv(jt + 2, (jt + 2) % 3);
        uint32_t st = sb + (jt % 3) * ASTAGE_B;

        // ---- S = Qh*K + Ql*K (log2 domain)
        float sacc[8][4];
#pragma unroll
        for (int j = 0; j < 8; j++)
#pragma unroll
            for (int e = 0; e < 4; e++) sacc[j][e] = 0.0f;
#pragma unroll
        for (int ks = 0; ks < 4; ks++) {
            uint32_t bt[8][2];
#pragma unroll
            for (int j2 = 0; j2 < 4; j2++) {
                uint32_t r0, r1, r2, r3;
                uint32_t addr = st + (kb_row + j2 * 16) * AROWB + ks * 32 + kb_kb;
                ldmatrix_x4(r0, r1, r2, r3, addr);
                bt[j2 * 2][0] = r0; bt[j2 * 2][1] = r1;
                bt[j2 * 2 + 1][0] = r2; bt[j2 * 2 + 1][1] = r3;
            }
#pragma unroll
            for (int j = 0; j < 8; j++)
                mma_f16(sacc[j], qh[ks][0], qh[ks][1], qh[ks][2], qh[ks][3],
                        bt[j][0], bt[j][1]);
#pragma unroll
            for (int j = 0; j < 8; j++)
                mma_f16(sacc[j], ql[ks][0], ql[ks][1], ql[ks][2], ql[ks][3],
                        bt[j][0], bt[j][1]);
        }

        // ---- online softmax (log2 domain, fp16 P via ex2.approx.f16x2)
        float mx0 = -1e30f, mx1 = -1e30f;
#pragma unroll
        for (int j = 0; j < 8; j++) {
            mx0 = fmaxf(mx0, fmaxf(sacc[j][0], sacc[j][1]));
            mx1 = fmaxf(mx1, fmaxf(sacc[j][2], sacc[j][3]));
        }
        mx0 = fmaxf(mx0, __shfl_xor_sync(0xffffffffu, mx0, 1));
        mx0 = fmaxf(mx0, __shfl_xor_sync(0xffffffffu, mx0, 2));
        mx1 = fmaxf(mx1, __shfl_xor_sync(0xffffffffu, mx1, 1));
        mx1 = fmaxf(mx1, __shfl_xor_sync(0xffffffffu, mx1, 2));
        float mn0 = fmaxf(mr0, mx0), mn1 = fmaxf(mr1, mx1);
        float al0 = exp2f(mr0 - mn0), al1 = exp2f(mr1 - mn1);
        mr0 = mn0; mr1 = mn1;

        uint32_t pfr[8][2];
        float sum0 = 0.0f, sum1 = 0.0f;
#pragma unroll
        for (int j = 0; j < 8; j++) {
            pfr[j][0] = ex2_f16x2(pack_h2(sacc[j][0] - mn0, sacc[j][1] - mn0));
            pfr[j][1] = ex2_f16x2(pack_h2(sacc[j][2] - mn1, sacc[j][3] - mn1));
            float2 f0 = __half22float2(*reinterpret_cast<__half2*>(&pfr[j][0]));
            float2 f1 = __half22float2(*reinterpret_cast<__half2*>(&pfr[j][1]));
            sum0 += f0.x + f0.y;
            sum1 += f1.x + f1.y;
        }
        sum0 += __shfl_xor_sync(0xffffffffu, sum0, 1);
        sum0 += __shfl_xor_sync(0xffffffffu, sum0, 2);
        sum1 += __shfl_xor_sync(0xffffffffu, sum1, 1);
        sum1 += __shfl_xor_sync(0xffffffffu, sum1, 2);
        lr0 = lr0 * al0 + sum0;
        lr1 = lr1 * al1 + sum1;
#pragma unroll
        for (int j = 0; j < 8; j++) {
            oacc[j][0] *= al0; oacc[j][1] *= al0;
            oacc[j][2] *= al1; oacc[j][3] *= al1;
        }

        // ---- O += P . V   (single product)
#pragma unroll
        for (int cs = 0; cs < 4; cs++) {
            int j0 = cs * 2, j1 = cs * 2 + 1;
            uint32_t vt[8][2];
#pragma unroll
            for (int jd2 = 0; jd2 < 4; jd2++) {
                uint32_t r0, r1, r2, r3;
                uint32_t addr = st + ATILE_B + (cs * 16 + v_row) * AROWB
                              + jd2 * 32 + v_cb;
                ldmatrix_x4_trans(r0, r1, r2, r3, addr);
                vt[jd2 * 2][0] = r0; vt[jd2 * 2][1] = r1;
                vt[jd2 * 2 + 1][0] = r2; vt[jd2 * 2 + 1][1] = r3;
            }
#pragma unroll
            for (int jd = 0; jd < 8; jd++)
                mma_f16(oacc[jd], pfr[j0][0], pfr[j0][1], pfr[j1][0], pfr[j1][1],
                        vt[jd][0], vt[jd][1]);
        }
    }

    // ---- epilogue: O/l -> g_O_hi / g_O_lo fp16 rows
    const int bq = bh >> 4;
    const int h  = bh & 15;
    float inv0 = 1.0f / lr0, inv1 = 1.0f / lr1;
#pragma unroll
    for (int e = 0; e < 2; e++) {
        int trow = t0 + wid * 16 + g + e * 8;
        float inv = e ? inv1 : inv0;
        size_t rowbase = (size_t)(bq * SEQ + trow) * KDIM + h * DHEAD;
#pragma unroll
        for (int jd = 0; jd < 8; jd++) {
            int d = jd * 8 + tq * 2;
            float v0 = oacc[jd][e * 2 + 0] * inv;
            float v1 = oacc[jd][e * 2 + 1] * inv;
            __half h0 = __float2half(v0), h1 = __float2half(v1);
            __half l0 = __float2half(v0 - __half2float(h0));
            __half l1 = __float2half(v1 - __half2float(h1));
            *reinterpret_cast<__half2*>(g_O_hi + rowbase + d) = __halves2half2(h0, h1);
            *reinterpret_cast<__half2*>(g_O_lo + rowbase + d) = __halves2half2(l0, l1);
        }
    }
}

// ---------------------------------------------------------------------------
extern "C" void kernel_launch(void* const* d_in, const int* in_sizes, int n_in,
                              void* d_out, int out_size) {
    const float* q   = (const float*)d_in[0];
    const float* kv  = (const float*)d_in[1];
    const float* Wq  = (const float*)d_in[2];
    const float* Wkv = (const float*)d_in[3];
    const float* W0  = (const float*)d_in[4];
    float* out = (float*)d_out;
    (void)in_sizes; (void)n_in; (void)out_size;

    (void)cudaFuncSetAttribute(attn_mma, cudaFuncAttributeMaxDynamicSharedMemorySize, ATTN_SMEM);
    (void)cudaFuncSetAttribute(gemm_mma<0>, cudaFuncAttributeMaxDynamicSharedMemorySize, GEMM_SMEM);
    (void)cudaFuncSetAttribute(gemm_mma<1>, cudaFuncAttributeMaxDynamicSharedMemorySize, GEMM_SMEM);
    (void)cudaFuncSetAttribute(gemm_mma<2>, cudaFuncAttributeMaxDynamicSharedMemorySize, GEMM_SMEM);

    split2<0><<<(MROWS * 512 + 255) / 256, 256>>>(q,  MROWS * 512);
    split2<1><<<(MROWS * 512 + 255) / 256, 256>>>(kv, MROWS * 512);
    cvt16<0><<<(1024 * 512 + 255) / 256, 256>>>(Wq,  1024 * 512);
    cvt16<1><<<(2048 * 512 + 255) / 256, 256>>>(Wkv, 2048 * 512);
    cvt16<2><<<(1024 * 512 + 255) / 256, 256>>>(W0,  1024 * 512);

    gemm_mma<0><<<dim3(EDIM / 128, MROWS / 128), 256, GEMM_SMEM>>>(nullptr);
    gemm_mma<1><<<dim3(2 * EDIM / 128, MROWS / 128), 256, GEMM_SMEM>>>(nullptr);
    attn_mma<<<dim3(SEQ / 128, BATCH * HEADS), 256, ATTN_SMEM>>>();
    gemm_mma<2><<<dim3(DMODEL / 128, MROWS / 128), 256, GEMM_SMEM>>>(out);
}

// round 14
// speedup vs baseline: 1.8832x; 1.1507x over previous
#include <cuda_runtime.h>
#include <cuda_bf16.h>
#include <cuda_fp16.h>
#include <cstdint>

// Problem constants
#define BATCH   4
#define SEQ     2048
#define DMODEL  1024
#define HEADS   16
#define DHEAD   64
#define EDIM    1024
#define MROWS   (BATCH * SEQ)     // 8192
#define KDIM    1024
#define QSCALE  (0.125f * 1.44269504088896340736f)   // 1/sqrt(64) * log2(e)

// ---------------------------------------------------------------------------
// Scratch (device globals; no allocation allowed)
// ---------------------------------------------------------------------------
__device__ __align__(256) __half g_Q [(size_t)BATCH * HEADS * SEQ * DHEAD];
__device__ __align__(256) __half g_K [(size_t)BATCH * HEADS * SEQ * DHEAD];
__device__ __align__(256) __half g_V [(size_t)BATCH * HEADS * SEQ * DHEAD];
__device__ __align__(256) __half g_q_hi [(size_t)MROWS * KDIM];
__device__ __align__(256) __half g_q_lo [(size_t)MROWS * KDIM];
__device__ __align__(256) __half g_kv_hi[(size_t)MROWS * KDIM];
__device__ __align__(256) __half g_kv_lo[(size_t)MROWS * KDIM];
__device__ __align__(256) __half g_O_hi [(size_t)MROWS * KDIM];
__device__ __align__(256) __half g_O_lo [(size_t)MROWS * KDIM];
__device__ __align__(256) __half g_Wq16 [(size_t)1024 * KDIM];
__device__ __align__(256) __half g_Wkv16[(size_t)2048 * KDIM];
__device__ __align__(256) __half g_W016 [(size_t)1024 * KDIM];

// ---------------------------------------------------------------------------
// Helpers
// ---------------------------------------------------------------------------
__device__ __forceinline__ uint32_t smem_u32(const void* p) {
    uint32_t a;
    asm("{ .reg .u64 t; cvta.to.shared.u64 t, %1; cvt.u32.u64 %0, t; }" : "=r"(a) : "l"(p));
    return a;
}
__device__ __forceinline__ void cp_async16(uint32_t smem_addr, const void* gptr) {
    asm volatile("cp.async.cg.shared.global [%0], [%1], 16;" :: "r"(smem_addr), "l"(gptr));
}
#define CP_COMMIT() asm volatile("cp.async.commit_group;" ::: "memory")
#define CP_WAIT(n)  asm volatile("cp.async.wait_group %0;" :: "n"(n) : "memory")

__device__ __forceinline__ void ldmatrix_x4(uint32_t& r0, uint32_t& r1, uint32_t& r2,
                                            uint32_t& r3, uint32_t addr) {
    asm volatile("ldmatrix.sync.aligned.m8n8.x4.shared.b16 {%0,%1,%2,%3}, [%4];"
                 : "=r"(r0), "=r"(r1), "=r"(r2), "=r"(r3) : "r"(addr));
}
__device__ __forceinline__ void ldmatrix_x4_trans(uint32_t& r0, uint32_t& r1, uint32_t& r2,
                                                  uint32_t& r3, uint32_t addr) {
    asm volatile("ldmatrix.sync.aligned.m8n8.x4.trans.shared.b16 {%0,%1,%2,%3}, [%4];"
                 : "=r"(r0), "=r"(r1), "=r"(r2), "=r"(r3) : "r"(addr));
}
__device__ __forceinline__ void mma_f16(float* c,
                                        uint32_t a0, uint32_t a1, uint32_t a2, uint32_t a3,
                                        uint32_t b0, uint32_t b1) {
    asm volatile(
        "mma.sync.aligned.m16n8k16.row.col.f32.f16.f16.f32 "
        "{%0,%1,%2,%3}, {%4,%5,%6,%7}, {%8,%9}, {%0,%1,%2,%3};"
        : "+f"(c[0]), "+f"(c[1]), "+f"(c[2]), "+f"(c[3])
        : "r"(a0), "r"(a1), "r"(a2), "r"(a3), "r"(b0), "r"(b1));
}
__device__ __forceinline__ uint32_t pack_h2(float x, float y) {
    __half2 t = __halves2half2(__float2half(x), __float2half(y));
    return *reinterpret_cast<uint32_t*>(&t);
}
__device__ __forceinline__ uint32_t ex2_f16x2(uint32_t x) {
    uint32_t r;
    asm volatile("ex2.approx.f16x2 %0, %1;" : "=r"(r) : "r"(x));
    return r;
}

// ---------------------------------------------------------------------------
// split2: fp32 [R,1024] -> fp16 hi + lo arrays.  0: q, 1: kv
// cvt16:  fp32 [R,1024] -> plain fp16.           0: Wq, 1: Wkv, 2: W0
// ---------------------------------------------------------------------------
template <int WHICH>
__global__ void split2(const float* __restrict__ src, int total2) {
    __half* dh = (WHICH == 0) ? g_q_hi : g_kv_hi;
    __half* dl = (WHICH == 0) ? g_q_lo : g_kv_lo;
    int idx = blockIdx.x * blockDim.x + threadIdx.x;
    if (idx >= total2) return;
    float2 v = *reinterpret_cast<const float2*>(src + (size_t)idx * 2);
    __half h0 = __float2half(v.x), h1 = __float2half(v.y);
    __half l0 = __float2half(v.x - __half2float(h0));
    __half l1 = __float2half(v.y - __half2float(h1));
    *reinterpret_cast<__half2*>(dh + (size_t)idx * 2) = __halves2half2(h0, h1);
    *reinterpret_cast<__half2*>(dl + (size_t)idx * 2) = __halves2half2(l0, l1);
}
template <int WHICH>
__global__ void cvt16(const float* __restrict__ src, int total2) {
    __half* dst = (WHICH == 0) ? g_Wq16 : (WHICH == 1) ? g_Wkv16 : g_W016;
    int idx = blockIdx.x * blockDim.x + threadIdx.x;
    if (idx >= total2) return;
    float2 v = *reinterpret_cast<const float2*>(src + (size_t)idx * 2);
    *reinterpret_cast<__half2*>(dst + (size_t)idx * 2) =
        __halves2half2(__float2half(v.x), __float2half(v.y));
}

// ---------------------------------------------------------------------------
// fp16 2-product TN GEMM: C = (Ah + Al) . W^T, K=1024, tile 128x128, BK=64.
// ---------------------------------------------------------------------------
#define GNCH        (KDIM / 64)          // 16
#define ROWB        144
#define TILE_B      (128 * ROWB)         // 18432
#define STAGE_B     (3 * TILE_B)         // 55296
#define GEMM_SMEM   (3 * STAGE_B)        // 165888

template <int MODE>
__global__ __launch_bounds__(256) void gemm_mma(float* __restrict__ C) {
    extern __shared__ char smem[];
    const uint32_t sb = smem_u32(smem);
    const int tid = threadIdx.x, wid = tid >> 5, lane = tid & 31;
    const int wm = wid >> 2, wn = wid & 3;
    const int m0 = blockIdx.y * 128, n0 = blockIdx.x * 128;

    const __half* Ah = (MODE == 0) ? g_q_hi : (MODE == 1) ? g_kv_hi : g_O_hi;
    const __half* Al = (MODE == 0) ? g_q_lo : (MODE == 1) ? g_kv_lo : g_O_lo;
    const __half* Wg = (MODE == 0) ? g_Wq16 : (MODE == 1) ? g_Wkv16 : g_W016;
    Ah += (size_t)m0 * KDIM;
    Al += (size_t)m0 * KDIM;
    Wg += (size_t)n0 * KDIM;

    float acc[4][4][4];
#pragma unroll
    for (int i = 0; i < 4; i++)
#pragma unroll
        for (int j = 0; j < 4; j++)
#pragma unroll
            for (int e = 0; e < 4; e++) acc[i][j][e] = 0.0f;

    auto load_stage = [&](int ch, int s) {
        uint32_t base = sb + s * STAGE_B;
#pragma unroll
        for (int t = 0; t < 12; t++) {
            int idx = tid + t * 256;
            int mat = idx >> 10;
            int rem = idx & 1023;
            int row = rem >> 3, ck = rem & 7;
            const __half* src = (mat == 0) ? Ah : (mat == 1) ? Al : Wg;
            cp_async16(base + mat * TILE_B + row * ROWB + ck * 16,
                       src + (size_t)row * KDIM + ch * 64 + ck * 8);
        }
        CP_COMMIT();
    };

    load_stage(0, 0);
    load_stage(1, 1);

    const uint32_t a_row = (uint32_t)(wm * 64 + (lane & 15));
    const uint32_t a_kb  = (uint32_t)(((lane >> 4) & 1) * 16);
    const uint32_t b_row = (uint32_t)(wn * 32 + (lane & 7) + ((lane >> 4) & 1) * 8);
    const uint32_t b_kb  = (uint32_t)(((lane >> 3) & 1) * 16);

    for (int ch = 0; ch < GNCH; ch++) {
        if (ch + 1 < GNCH) { CP_WAIT(1); } else { CP_WAIT(0); }
        __syncthreads();
        if (ch + 2 < GNCH) load_stage(ch + 2, (ch + 2) % 3);

        uint32_t hBase = sb + (ch % 3) * STAGE_B;
        uint32_t lBase = hBase + TILE_B;
        uint32_t wBase = hBase + 2 * TILE_B;
#pragma unroll
        for (int ks = 0; ks < 4; ks++) {
            uint32_t ah[4][4], al[4][4], b[4][2];
#pragma unroll
            for (int i = 0; i < 4; i++) {
                uint32_t off = (a_row + i * 16) * ROWB + ks * 32 + a_kb;
                ldmatrix_x4(ah[i][0], ah[i][1], ah[i][2], ah[i][3], hBase + off);
                ldmatrix_x4(al[i][0], al[i][1], al[i][2], al[i][3], lBase + off);
            }
#pragma unroll
            for (int j2 = 0; j2 < 2; j2++) {
                uint32_t r0, r1, r2, r3;
                uint32_t addr = wBase + (b_row + j2 * 16) * ROWB + ks * 32 + b_kb;
                ldmatrix_x4(r0, r1, r2, r3, addr);
                b[j2 * 2][0] = r0; b[j2 * 2][1] = r1;
                b[j2 * 2 + 1][0] = r2; b[j2 * 2 + 1][1] = r3;
            }
#pragma unroll
            for (int i = 0; i < 4; i++)
#pragma unroll
                for (int j = 0; j < 4; j++)
                    mma_f16(acc[i][j], ah[i][0], ah[i][1], ah[i][2], ah[i][3],
                            b[j][0], b[j][1]);
#pragma unroll
            for (int i = 0; i < 4; i++)
#pragma unroll
                for (int j = 0; j < 4; j++)
                    mma_f16(acc[i][j], al[i][0], al[i][1], al[i][2], al[i][3],
                            b[j][0], b[j][1]);
        }
    }

    const int g = lane >> 2, tq = lane & 3;
#pragma unroll
    for (int i = 0; i < 4; i++) {
#pragma unroll
        for (int e = 0; e < 2; e++) {
            int m = m0 + wm * 64 + i * 16 + g + e * 8;
            int b = m >> 11;
            int t = m & 2047;
#pragma unroll
            for (int j = 0; j < 4; j++) {
#pragma unroll
                for (int x = 0; x < 2; x++) {
                    int n = n0 + wn * 32 + j * 8 + tq * 2 + x;
                    float v = acc[i][j][e * 2 + x];
                    if (MODE == 0) {
                        int d = n >> 4, h = n & 15;
                        size_t a5 = ((((size_t)b * HEADS + h) * SEQ + t) << 6) + d;
                        g_Q[a5] = __float2half(v * QSCALE);   // log2-domain scale
                    } else if (MODE == 1) {
                        int h = n & 15, kk = (n >> 4) & 1, d = n >> 5;
                        size_t a5 = ((((size_t)b * HEADS + h) * SEQ + t) << 6) + d;
                        if (kk) g_V[a5] = __float2half(v);
                        else    g_K[a5] = __float2half(v);
                    } else {
                        C[(size_t)m * 1024 + n] = v;
                    }
                }
            }
        }
    }
}

// ---------------------------------------------------------------------------
// Flash attention, fp16 single-product QK, log2-domain softmax (ex2.f16x2):
//   S = Q . K            (Q plain fp16, pre-scaled 0.125*log2e)
//   P = 2^(S - m)        (fp16 via ex2.approx.f16x2)
//   O = P . V            (single product)
// CTA: 128 q-rows, 8 warps, key tiles of 64; 3-stage KV ring, 1 barrier/tile.
// ---------------------------------------------------------------------------
#define AROWB    144
#define ATILE_B  (64 * AROWB)            // 9216
#define ASTAGE_B (2 * ATILE_B)           // 18432  (K | V)
#define ATTN_SMEM (3 * ASTAGE_B)         // 55296

__global__ __launch_bounds__(256) void attn_mma() {
    extern __shared__ char smem[];
    const uint32_t sb = smem_u32(smem);
    const int tid = threadIdx.x, wid = tid >> 5, lane = tid & 31;
    const int g = lane >> 2, tq = lane & 3;
    const int bh = blockIdx.y;
    const int t0 = blockIdx.x << 7;

    const size_t bhoff = (size_t)bh * SEQ * DHEAD;
    const __half* Qg = g_Q + bhoff + (size_t)t0 * DHEAD;
    const __half* Kg = g_K + bhoff;
    const __half* Vg = g_V + bhoff;

    // ---- Stage Q (128 rows x 64 fp16) in stage-0 smem, extract fragments
#pragma unroll
    for (int t = 0; t < 4; t++) {
        int idx = tid + t * 256;             // 0..1023
        int r   = idx >> 3;
        int ck  = idx & 7;
        cp_async16(sb + r * AROWB + ck * 16, Qg + (size_t)r * DHEAD + ck * 8);
    }
    CP_COMMIT();
    CP_WAIT(0);
    __syncthreads();

    uint32_t qf[4][4];
    {
        uint32_t qrow = (uint32_t)(wid * 16 + (lane & 15));
        uint32_t kb   = (uint32_t)(((lane >> 4) & 1) * 16);
#pragma unroll
        for (int ks = 0; ks < 4; ks++) {
            uint32_t addr = sb + qrow * AROWB + ks * 32 + kb;
            ldmatrix_x4(qf[ks][0], qf[ks][1], qf[ks][2], qf[ks][3], addr);
        }
    }
    __syncthreads();

    auto load_kv = [&](int jt, int s) {
        uint32_t base = sb + s * ASTAGE_B;
#pragma unroll
        for (int t = 0; t < 4; t++) {
            int idx = tid + t * 256;
            int mat = idx >> 9;
            int r   = (idx >> 3) & 63;
            int ck  = idx & 7;
            const __half* src = mat ? Vg : Kg;
            cp_async16(base + mat * ATILE_B + r * AROWB + ck * 16,
                       src + (size_t)(jt * 64 + r) * DHEAD + ck * 8);
        }
        CP_COMMIT();
    };

    load_kv(0, 0);
    load_kv(1, 1);

    float oacc[8][4];
#pragma unroll
    for (int j = 0; j < 8; j++)
#pragma unroll
        for (int e = 0; e < 4; e++) oacc[j][e] = 0.0f;
    float mr0 = -1e30f, mr1 = -1e30f, lr0 = 0.0f, lr1 = 0.0f;

    const uint32_t kb_row = (uint32_t)((lane & 7) + ((lane >> 4) & 1) * 8);
    const uint32_t kb_kb  = (uint32_t)(((lane >> 3) & 1) * 16);
    const uint32_t v_row  = (uint32_t)((lane & 7) + ((lane >> 3) & 1) * 8);
    const uint32_t v_cb   = (uint32_t)(((lane >> 4) & 1) * 8 * 2);

    for (int jt = 0; jt < SEQ / 64; jt++) {
        if (jt + 1 < SEQ / 64) { CP_WAIT(1); } else { CP_WAIT(0); }
        __syncthreads();
        if (jt + 2 < SEQ / 64) load_kv(jt + 2, (jt + 2) % 3);
        uint32_t st = sb + (jt % 3) * ASTAGE_B;

        // ---- S = Q * K (log2 domain, single product)
        float sacc[8][4];
#pragma unroll
        for (int j = 0; j < 8; j++)
#pragma unroll
            for (int e = 0; e < 4; e++) sacc[j][e] = 0.0f;
#pragma unroll
        for (int ks = 0; ks < 4; ks++) {
            uint32_t bt[8][2];
#pragma unroll
            for (int j2 = 0; j2 < 4; j2++) {
                uint32_t r0, r1, r2, r3;
                uint32_t addr = st + (kb_row + j2 * 16) * AROWB + ks * 32 + kb_kb;
                ldmatrix_x4(r0, r1, r2, r3, addr);
                bt[j2 * 2][0] = r0; bt[j2 * 2][1] = r1;
                bt[j2 * 2 + 1][0] = r2; bt[j2 * 2 + 1][1] = r3;
            }
#pragma unroll
            for (int j = 0; j < 8; j++)
                mma_f16(sacc[j], qf[ks][0], qf[ks][1], qf[ks][2], qf[ks][3],
                        bt[j][0], bt[j][1]);
        }

        // ---- online softmax (log2 domain, fp16 P via ex2.approx.f16x2)
        float mx0 = -1e30f, mx1 = -1e30f;
#pragma unroll
        for (int j = 0; j < 8; j++) {
            mx0 = fmaxf(mx0, fmaxf(sacc[j][0], sacc[j][1]));
            mx1 = fmaxf(mx1, fmaxf(sacc[j][2], sacc[j][3]));
        }
        mx0 = fmaxf(mx0, __shfl_xor_sync(0xffffffffu, mx0, 1));
        mx0 = fmaxf(mx0, __shfl_xor_sync(0xffffffffu, mx0, 2));
        mx1 = fmaxf(mx1, __shfl_xor_sync(0xffffffffu, mx1, 1));
        mx1 = fmaxf(mx1, __shfl_xor_sync(0xffffffffu, mx1, 2));
        float mn0 = fmaxf(mr0, mx0), mn1 = fmaxf(mr1, mx1);
        float al0 = exp2f(mr0 - mn0), al1 = exp2f(mr1 - mn1);
        mr0 = mn0; mr1 = mn1;

        uint32_t pfr[8][2];
        float sum0 = 0.0f, sum1 = 0.0f;
#pragma unroll
        for (int j = 0; j < 8; j++) {
            pfr[j][0] = ex2_f16x2(pack_h2(sacc[j][0] - mn0, sacc[j][1] - mn0));
            pfr[j][1] = ex2_f16x2(pack_h2(sacc[j][2] - mn1, sacc[j][3] - mn1));
            float2 f0 = __half22float2(*reinterpret_cast<__half2*>(&pfr[j][0]));
            float2 f1 = __half22float2(*reinterpret_cast<__half2*>(&pfr[j][1]));
            sum0 += f0.x + f0.y;
            sum1 += f1.x + f1.y;
        }
        sum0 += __shfl_xor_sync(0xffffffffu, sum0, 1);
        sum0 += __shfl_xor_sync(0xffffffffu, sum0, 2);
        sum1 += __shfl_xor_sync(0xffffffffu, sum1, 1);
        sum1 += __shfl_xor_sync(0xffffffffu, sum1, 2);
        lr0 = lr0 * al0 + sum0;
        lr1 = lr1 * al1 + sum1;
#pragma unroll
        for (int j = 0; j < 8; j++) {
            oacc[j][0] *= al0; oacc[j][1] *= al0;
            oacc[j][2] *= al1; oacc[j][3] *= al1;
        }

        // ---- O += P . V   (single product)
#pragma unroll
        for (int cs = 0; cs < 4; cs++) {
            int j0 = cs * 2, j1 = cs * 2 + 1;
            uint32_t vt[8][2];
#pragma unroll
            for (int jd2 = 0; jd2 < 4; jd2++) {
                uint32_t r0, r1, r2, r3;
                uint32_t addr = st + ATILE_B + (cs * 16 + v_row) * AROWB
                              + jd2 * 32 + v_cb;
                ldmatrix_x4_trans(r0, r1, r2, r3, addr);
                vt[jd2 * 2][0] = r0; vt[jd2 * 2][1] = r1;
                vt[jd2 * 2 + 1][0] = r2; vt[jd2 * 2 + 1][1] = r3;
            }
#pragma unroll
            for (int jd = 0; jd < 8; jd++)
                mma_f16(oacc[jd], pfr[j0][0], pfr[j0][1], pfr[j1][0], pfr[j1][1],
                        vt[jd][0], vt[jd][1]);
        }
    }

    // ---- epilogue: O/l -> g_O_hi / g_O_lo fp16 rows
    const int bq = bh >> 4;
    const int h  = bh & 15;
    float inv0 = 1.0f / lr0, inv1 = 1.0f / lr1;
#pragma unroll
    for (int e = 0; e < 2; e++) {
        int trow = t0 + wid * 16 + g + e * 8;
        float inv = e ? inv1 : inv0;
        size_t rowbase = (size_t)(bq * SEQ + trow) * KDIM + h * DHEAD;
#pragma unroll
        for (int jd = 0; jd < 8; jd++) {
            int d = jd * 8 + tq * 2;
            float v0 = oacc[jd][e * 2 + 0] * inv;
            float v1 = oacc[jd][e * 2 + 1] * inv;
            __half h0 = __float2half(v0), h1 = __float2half(v1);
            __half l0 = __float2half(v0 - __half2float(h0));
            __half l1 = __float2half(v1 - __half2float(h1));
            *reinterpret_cast<__half2*>(g_O_hi + rowbase + d) = __halves2half2(h0, h1);
            *reinterpret_cast<__half2*>(g_O_lo + rowbase + d) = __halves2half2(l0, l1);
        }
    }
}

// ---------------------------------------------------------------------------
extern "C" void kernel_launch(void* const* d_in, const int* in_sizes, int n_in,
                              void* d_out, int out_size) {
    const float* q   = (const float*)d_in[0];
    const float* kv  = (const float*)d_in[1];
    const float* Wq  = (const float*)d_in[2];
    const float* Wkv = (const float*)d_in[3];
    const float* W0  = (const float*)d_in[4];
    float* out = (float*)d_out;
    (void)in_sizes; (void)n_in; (void)out_size;

    (void)cudaFuncSetAttribute(attn_mma, cudaFuncAttributeMaxDynamicSharedMemorySize, ATTN_SMEM);
    (void)cudaFuncSetAttribute(gemm_mma<0>, cudaFuncAttributeMaxDynamicSharedMemorySize, GEMM_SMEM);
    (void)cudaFuncSetAttribute(gemm_mma<1>, cudaFuncAttributeMaxDynamicSharedMemorySize, GEMM_SMEM);
    (void)cudaFuncSetAttribute(gemm_mma<2>, cudaFuncAttributeMaxDynamicSharedMemorySize, GEMM_SMEM);

    split2<0><<<(MROWS * 512 + 255) / 256, 256>>>(q,  MROWS * 512);
    split2<1><<<(MROWS * 512 + 255) / 256, 256>>>(kv, MROWS * 512);
    cvt16<0><<<(1024 * 512 + 255) / 256, 256>>>(Wq,  1024 * 512);
    cvt16<1><<<(2048 * 512 + 255) / 256, 256>>>(Wkv, 2048 * 512);
    cvt16<2><<<(1024 * 512 + 255) / 256, 256>>>(W0,  1024 * 512);

    gemm_mma<0><<<dim3(EDIM / 128, MROWS / 128), 256, GEMM_SMEM>>>(nullptr);
    gemm_mma<1><<<dim3(2 * EDIM / 128, MROWS / 128), 256, GEMM_SMEM>>>(nullptr);
    attn_mma<<<dim3(SEQ / 128, BATCH * HEADS), 256, ATTN_SMEM>>>();
    gemm_mma<2><<<dim3(DMODEL / 128, MROWS / 128), 256, GEMM_SMEM>>>(out);
}

// round 15
// speedup vs baseline: 2.3893x; 1.2687x over previous
#include <cuda_runtime.h>
#include <cuda_bf16.h>
#include <cuda_fp16.h>
#include <cstdint>

// Problem constants
#define BATCH   4
#define SEQ     2048
#define DMODEL  1024
#define HEADS   16
#define DHEAD   64
#define EDIM    1024
#define MROWS   (BATCH * SEQ)     // 8192
#define KDIM    1024
#define QSCALE  (0.125f * 1.44269504088896340736f)   // 1/sqrt(64) * log2(e)

// ---------------------------------------------------------------------------
// Scratch (device globals; no allocation allowed)
// ---------------------------------------------------------------------------
__device__ __align__(256) __half g_Q [(size_t)BATCH * HEADS * SEQ * DHEAD];
__device__ __align__(256) __half g_K [(size_t)BATCH * HEADS * SEQ * DHEAD];
__device__ __align__(256) __half g_V [(size_t)BATCH * HEADS * SEQ * DHEAD];
// GEMM operands, plain fp16
__device__ __align__(256) __half g_Xq [(size_t)MROWS * KDIM];
__device__ __align__(256) __half g_Xkv[(size_t)MROWS * KDIM];
__device__ __align__(256) __half g_O  [(size_t)MROWS * KDIM];
__device__ __align__(256) __half g_Wq16 [(size_t)1024 * KDIM];
__device__ __align__(256) __half g_Wkv16[(size_t)2048 * KDIM];
__device__ __align__(256) __half g_W016 [(size_t)1024 * KDIM];

// ---------------------------------------------------------------------------
// Helpers
// ---------------------------------------------------------------------------
__device__ __forceinline__ uint32_t smem_u32(const void* p) {
    uint32_t a;
    asm("{ .reg .u64 t; cvta.to.shared.u64 t, %1; cvt.u32.u64 %0, t; }" : "=r"(a) : "l"(p));
    return a;
}
__device__ __forceinline__ void cp_async16(uint32_t smem_addr, const void* gptr) {
    asm volatile("cp.async.cg.shared.global [%0], [%1], 16;" :: "r"(smem_addr), "l"(gptr));
}
#define CP_COMMIT() asm volatile("cp.async.commit_group;" ::: "memory")
#define CP_WAIT(n)  asm volatile("cp.async.wait_group %0;" :: "n"(n) : "memory")

__device__ __forceinline__ void ldmatrix_x4(uint32_t& r0, uint32_t& r1, uint32_t& r2,
                                            uint32_t& r3, uint32_t addr) {
    asm volatile("ldmatrix.sync.aligned.m8n8.x4.shared.b16 {%0,%1,%2,%3}, [%4];"
                 : "=r"(r0), "=r"(r1), "=r"(r2), "=r"(r3) : "r"(addr));
}
__device__ __forceinline__ void ldmatrix_x4_trans(uint32_t& r0, uint32_t& r1, uint32_t& r2,
                                                  uint32_t& r3, uint32_t addr) {
    asm volatile("ldmatrix.sync.aligned.m8n8.x4.trans.shared.b16 {%0,%1,%2,%3}, [%4];"
                 : "=r"(r0), "=r"(r1), "=r"(r2), "=r"(r3) : "r"(addr));
}
__device__ __forceinline__ void mma_f16(float* c,
                                        uint32_t a0, uint32_t a1, uint32_t a2, uint32_t a3,
                                        uint32_t b0, uint32_t b1) {
    asm volatile(
        "mma.sync.aligned.m16n8k16.row.col.f32.f16.f16.f32 "
        "{%0,%1,%2,%3}, {%4,%5,%6,%7}, {%8,%9}, {%0,%1,%2,%3};"
        : "+f"(c[0]), "+f"(c[1]), "+f"(c[2]), "+f"(c[3])
        : "r"(a0), "r"(a1), "r"(a2), "r"(a3), "r"(b0), "r"(b1));
}
__device__ __forceinline__ uint32_t pack_h2(float x, float y) {
    __half2 t = __halves2half2(__float2half(x), __float2half(y));
    return *reinterpret_cast<uint32_t*>(&t);
}
__device__ __forceinline__ uint32_t ex2_f16x2(uint32_t x) {
    uint32_t r;
    asm volatile("ex2.approx.f16x2 %0, %1;" : "=r"(r) : "r"(x));
    return r;
}

// ---------------------------------------------------------------------------
// cvt16: fp32 [R,1024] -> plain fp16.
// 0: q -> g_Xq, 1: kv -> g_Xkv, 2: Wq, 3: Wkv, 4: W0
// ---------------------------------------------------------------------------
template <int WHICH>
__global__ void cvt16(const float* __restrict__ src, int total2) {
    __half* dst = (WHICH == 0) ? g_Xq : (WHICH == 1) ? g_Xkv :
                  (WHICH == 2) ? g_Wq16 : (WHICH == 3) ? g_Wkv16 : g_W016;
    int idx = blockIdx.x * blockDim.x + threadIdx.x;
    if (idx >= total2) return;
    float2 v = *reinterpret_cast<const float2*>(src + (size_t)idx * 2);
    *reinterpret_cast<__half2*>(dst + (size_t)idx * 2) =
        __halves2half2(__float2half(v.x), __float2half(v.y));
}

// ---------------------------------------------------------------------------
// fp16 single-product TN GEMM: C = A . W^T, K=1024, tile 128x128, BK=64.
// Stage = [A | W] tiles; 3-stage ring, ONE barrier per chunk.
// MODE 0: A=Xq,  W=Wq,  scatter n=(d*16+h)       -> g_Q (x QSCALE)
// MODE 1: A=Xkv, W=Wkv, scatter n=(d*32+kk*16+h) -> g_K / g_V
// MODE 2: A=g_O, W=W0,  C[m*1024+n] = v (d_out)
// ---------------------------------------------------------------------------
#define GNCH        (KDIM / 64)          // 16
#define ROWB        144
#define TILE_B      (128 * ROWB)         // 18432
#define STAGE_B     (2 * TILE_B)         // 36864
#define GEMM_SMEM   (3 * STAGE_B)        // 110592

template <int MODE>
__global__ __launch_bounds__(256) void gemm_mma(float* __restrict__ C) {
    extern __shared__ char smem[];
    const uint32_t sb = smem_u32(smem);
    const int tid = threadIdx.x, wid = tid >> 5, lane = tid & 31;
    const int wm = wid >> 2, wn = wid & 3;
    const int m0 = blockIdx.y * 128, n0 = blockIdx.x * 128;

    const __half* Ag = (MODE == 0) ? g_Xq : (MODE == 1) ? g_Xkv : g_O;
    const __half* Wg = (MODE == 0) ? g_Wq16 : (MODE == 1) ? g_Wkv16 : g_W016;
    Ag += (size_t)m0 * KDIM;
    Wg += (size_t)n0 * KDIM;

    float acc[4][4][4];
#pragma unroll
    for (int i = 0; i < 4; i++)
#pragma unroll
        for (int j = 0; j < 4; j++)
#pragma unroll
            for (int e = 0; e < 4; e++) acc[i][j][e] = 0.0f;

    auto load_stage = [&](int ch, int s) {
        uint32_t base = sb + s * STAGE_B;
#pragma unroll
        for (int t = 0; t < 8; t++) {
            int idx = tid + t * 256;            // 0..2047
            int op  = idx >> 10;                // 0=A,1=W
            int row = (idx >> 3) & 127;
            int ck  = idx & 7;
            const __half* src = op ? Wg : Ag;
            cp_async16(base + op * TILE_B + row * ROWB + ck * 16,
                       src + (size_t)row * KDIM + ch * 64 + ck * 8);
        }
        CP_COMMIT();
    };

    load_stage(0, 0);
    load_stage(1, 1);

    const uint32_t a_row = (uint32_t)(wm * 64 + (lane & 15));
    const uint32_t a_kb  = (uint32_t)(((lane >> 4) & 1) * 16);
    const uint32_t b_row = (uint32_t)(wn * 32 + (lane & 7) + ((lane >> 4) & 1) * 8);
    const uint32_t b_kb  = (uint32_t)(((lane >> 3) & 1) * 16);

    for (int ch = 0; ch < GNCH; ch++) {
        if (ch + 1 < GNCH) { CP_WAIT(1); } else { CP_WAIT(0); }
        __syncthreads();
        if (ch + 2 < GNCH) load_stage(ch + 2, (ch + 2) % 3);

        uint32_t aBase = sb + (ch % 3) * STAGE_B;
        uint32_t wBase = aBase + TILE_B;
#pragma unroll
        for (int ks = 0; ks < 4; ks++) {
            uint32_t a[4][4], b[4][2];
#pragma unroll
            for (int i = 0; i < 4; i++) {
                uint32_t off = (a_row + i * 16) * ROWB + ks * 32 + a_kb;
                ldmatrix_x4(a[i][0], a[i][1], a[i][2], a[i][3], aBase + off);
            }
#pragma unroll
            for (int j2 = 0; j2 < 2; j2++) {
                uint32_t r0, r1, r2, r3;
                uint32_t addr = wBase + (b_row + j2 * 16) * ROWB + ks * 32 + b_kb;
                ldmatrix_x4(r0, r1, r2, r3, addr);
                b[j2 * 2][0] = r0; b[j2 * 2][1] = r1;
                b[j2 * 2 + 1][0] = r2; b[j2 * 2 + 1][1] = r3;
            }
#pragma unroll
            for (int i = 0; i < 4; i++)
#pragma unroll
                for (int j = 0; j < 4; j++)
                    mma_f16(acc[i][j], a[i][0], a[i][1], a[i][2], a[i][3],
                            b[j][0], b[j][1]);
        }
    }

    const int g = lane >> 2, tq = lane & 3;
#pragma unroll
    for (int i = 0; i < 4; i++) {
#pragma unroll
        for (int e = 0; e < 2; e++) {
            int m = m0 + wm * 64 + i * 16 + g + e * 8;
            int b = m >> 11;
            int t = m & 2047;
#pragma unroll
            for (int j = 0; j < 4; j++) {
#pragma unroll
                for (int x = 0; x < 2; x++) {
                    int n = n0 + wn * 32 + j * 8 + tq * 2 + x;
                    float v = acc[i][j][e * 2 + x];
                    if (MODE == 0) {
                        int d = n >> 4, h = n & 15;
                        size_t a5 = ((((size_t)b * HEADS + h) * SEQ + t) << 6) + d;
                        g_Q[a5] = __float2half(v * QSCALE);
                    } else if (MODE == 1) {
                        int h = n & 15, kk = (n >> 4) & 1, d = n >> 5;
                        size_t a5 = ((((size_t)b * HEADS + h) * SEQ + t) << 6) + d;
                        if (kk) g_V[a5] = __float2half(v);
                        else    g_K[a5] = __float2half(v);
                    } else {
                        C[(size_t)m * 1024 + n] = v;
                    }
                }
            }
        }
    }
}

// ---------------------------------------------------------------------------
// Flash attention, fp16 single-product QK, log2-domain softmax (ex2.f16x2):
//   S = Q . K ;  P = 2^(S-m) fp16 ;  O = P . V
// CTA: 128 q-rows, 8 warps, key tiles of 64; 3-stage KV ring, 1 barrier/tile.
// ---------------------------------------------------------------------------
#define AROWB    144
#define ATILE_B  (64 * AROWB)            // 9216
#define ASTAGE_B (2 * ATILE_B)           // 18432  (K | V)
#define ATTN_SMEM (3 * ASTAGE_B)         // 55296

__global__ __launch_bounds__(256) void attn_mma() {
    extern __shared__ char smem[];
    const uint32_t sb = smem_u32(smem);
    const int tid = threadIdx.x, wid = tid >> 5, lane = tid & 31;
    const int g = lane >> 2, tq = lane & 3;
    const int bh = blockIdx.y;
    const int t0 = blockIdx.x << 7;

    const size_t bhoff = (size_t)bh * SEQ * DHEAD;
    const __half* Qg = g_Q + bhoff + (size_t)t0 * DHEAD;
    const __half* Kg = g_K + bhoff;
    const __half* Vg = g_V + bhoff;

    // ---- Stage Q (128 rows x 64 fp16), extract fragments
#pragma unroll
    for (int t = 0; t < 4; t++) {
        int idx = tid + t * 256;             // 0..1023
        int r   = idx >> 3;
        int ck  = idx & 7;
        cp_async16(sb + r * AROWB + ck * 16, Qg + (size_t)r * DHEAD + ck * 8);
    }
    CP_COMMIT();
    CP_WAIT(0);
    __syncthreads();

    uint32_t qf[4][4];
    {
        uint32_t qrow = (uint32_t)(wid * 16 + (lane & 15));
        uint32_t kb   = (uint32_t)(((lane >> 4) & 1) * 16);
#pragma unroll
        for (int ks = 0; ks < 4; ks++) {
            uint32_t addr = sb + qrow * AROWB + ks * 32 + kb;
            ldmatrix_x4(qf[ks][0], qf[ks][1], qf[ks][2], qf[ks][3], addr);
        }
    }
    __syncthreads();

    auto load_kv = [&](int jt, int s) {
        uint32_t base = sb + s * ASTAGE_B;
#pragma unroll
        for (int t = 0; t < 4; t++) {
            int idx = tid + t * 256;
            int mat = idx >> 9;
            int r   = (idx >> 3) & 63;
            int ck  = idx & 7;
            const __half* src = mat ? Vg : Kg;
            cp_async16(base + mat * ATILE_B + r * AROWB + ck * 16,
                       src + (size_t)(jt * 64 + r) * DHEAD + ck * 8);
        }
        CP_COMMIT();
    };

    load_kv(0, 0);
    load_kv(1, 1);

    float oacc[8][4];
#pragma unroll
    for (int j = 0; j < 8; j++)
#pragma unroll
        for (int e = 0; e < 4; e++) oacc[j][e] = 0.0f;
    float mr0 = -1e30f, mr1 = -1e30f, lr0 = 0.0f, lr1 = 0.0f;

    const uint32_t kb_row = (uint32_t)((lane & 7) + ((lane >> 4) & 1) * 8);
    const uint32_t kb_kb  = (uint32_t)(((lane >> 3) & 1) * 16);
    const uint32_t v_row  = (uint32_t)((lane & 7) + ((lane >> 3) & 1) * 8);
    const uint32_t v_cb   = (uint32_t)(((lane >> 4) & 1) * 8 * 2);

    for (int jt = 0; jt < SEQ / 64; jt++) {
        if (jt + 1 < SEQ / 64) { CP_WAIT(1); } else { CP_WAIT(0); }
        __syncthreads();
        if (jt + 2 < SEQ / 64) load_kv(jt + 2, (jt + 2) % 3);
        uint32_t st = sb + (jt % 3) * ASTAGE_B;

        // ---- S = Q * K (log2 domain)
        float sacc[8][4];
#pragma unroll
        for (int j = 0; j < 8; j++)
#pragma unroll
            for (int e = 0; e < 4; e++) sacc[j][e] = 0.0f;
#pragma unroll
        for (int ks = 0; ks < 4; ks++) {
            uint32_t bt[8][2];
#pragma unroll
            for (int j2 = 0; j2 < 4; j2++) {
                uint32_t r0, r1, r2, r3;
                uint32_t addr = st + (kb_row + j2 * 16) * AROWB + ks * 32 + kb_kb;
                ldmatrix_x4(r0, r1, r2, r3, addr);
                bt[j2 * 2][0] = r0; bt[j2 * 2][1] = r1;
                bt[j2 * 2 + 1][0] = r2; bt[j2 * 2 + 1][1] = r3;
            }
#pragma unroll
            for (int j = 0; j < 8; j++)
                mma_f16(sacc[j], qf[ks][0], qf[ks][1], qf[ks][2], qf[ks][3],
                        bt[j][0], bt[j][1]);
        }

        // ---- online softmax (log2 domain, fp16 P via ex2.approx.f16x2)
        float mx0 = -1e30f, mx1 = -1e30f;
#pragma unroll
        for (int j = 0; j < 8; j++) {
            mx0 = fmaxf(mx0, fmaxf(sacc[j][0], sacc[j][1]));
            mx1 = fmaxf(mx1, fmaxf(sacc[j][2], sacc[j][3]));
        }
        mx0 = fmaxf(mx0, __shfl_xor_sync(0xffffffffu, mx0, 1));
        mx0 = fmaxf(mx0, __shfl_xor_sync(0xffffffffu, mx0, 2));
        mx1 = fmaxf(mx1, __shfl_xor_sync(0xffffffffu, mx1, 1));
        mx1 = fmaxf(mx1, __shfl_xor_sync(0xffffffffu, mx1, 2));
        float mn0 = fmaxf(mr0, mx0), mn1 = fmaxf(mr1, mx1);
        float al0 = exp2f(mr0 - mn0), al1 = exp2f(mr1 - mn1);
        mr0 = mn0; mr1 = mn1;

        uint32_t pfr[8][2];
        float sum0 = 0.0f, sum1 = 0.0f;
#pragma unroll
        for (int j = 0; j < 8; j++) {
            pfr[j][0] = ex2_f16x2(pack_h2(sacc[j][0] - mn0, sacc[j][1] - mn0));
            pfr[j][1] = ex2_f16x2(pack_h2(sacc[j][2] - mn1, sacc[j][3] - mn1));
            float2 f0 = __half22float2(*reinterpret_cast<__half2*>(&pfr[j][0]));
            float2 f1 = __half22float2(*reinterpret_cast<__half2*>(&pfr[j][1]));
            sum0 += f0.x + f0.y;
            sum1 += f1.x + f1.y;
        }
        sum0 += __shfl_xor_sync(0xffffffffu, sum0, 1);
        sum0 += __shfl_xor_sync(0xffffffffu, sum0, 2);
        sum1 += __shfl_xor_sync(0xffffffffu, sum1, 1);
        sum1 += __shfl_xor_sync(0xffffffffu, sum1, 2);
        lr0 = lr0 * al0 + sum0;
        lr1 = lr1 * al1 + sum1;
#pragma unroll
        for (int j = 0; j < 8; j++) {
            oacc[j][0] *= al0; oacc[j][1] *= al0;
            oacc[j][2] *= al1; oacc[j][3] *= al1;
        }

        // ---- O += P . V
#pragma unroll
        for (int cs = 0; cs < 4; cs++) {
            int j0 = cs * 2, j1 = cs * 2 + 1;
            uint32_t vt[8][2];
#pragma unroll
            for (int jd2 = 0; jd2 < 4; jd2++) {
                uint32_t r0, r1, r2, r3;
                uint32_t addr = st + ATILE_B + (cs * 16 + v_row) * AROWB
                              + jd2 * 32 + v_cb;
                ldmatrix_x4_trans(r0, r1, r2, r3, addr);
                vt[jd2 * 2][0] = r0; vt[jd2 * 2][1] = r1;
                vt[jd2 * 2 + 1][0] = r2; vt[jd2 * 2 + 1][1] = r3;
            }
#pragma unroll
            for (int jd = 0; jd < 8; jd++)
                mma_f16(oacc[jd], pfr[j0][0], pfr[j0][1], pfr[j1][0], pfr[j1][1],
                        vt[jd][0], vt[jd][1]);
        }
    }

    // ---- epilogue: O/l -> g_O plain fp16 rows
    const int bq = bh >> 4;
    const int h  = bh & 15;
    float inv0 = 1.0f / lr0, inv1 = 1.0f / lr1;
#pragma unroll
    for (int e = 0; e < 2; e++) {
        int trow = t0 + wid * 16 + g + e * 8;
        float inv = e ? inv1 : inv0;
        size_t rowbase = (size_t)(bq * SEQ + trow) * KDIM + h * DHEAD;
#pragma unroll
        for (int jd = 0; jd < 8; jd++) {
            int d = jd * 8 + tq * 2;
            float v0 = oacc[jd][e * 2 + 0] * inv;
            float v1 = oacc[jd][e * 2 + 1] * inv;
            *reinterpret_cast<__half2*>(g_O + rowbase + d) =
                __halves2half2(__float2half(v0), __float2half(v1));
        }
    }
}

// ---------------------------------------------------------------------------
extern "C" void kernel_launch(void* const* d_in, const int* in_sizes, int n_in,
                              void* d_out, int out_size) {
    const float* q   = (const float*)d_in[0];
    const float* kv  = (const float*)d_in[1];
    const float* Wq  = (const float*)d_in[2];
    const float* Wkv = (const float*)d_in[3];
    const float* W0  = (const float*)d_in[4];
    float* out = (float*)d_out;
    (void)in_sizes; (void)n_in; (void)out_size;

    (void)cudaFuncSetAttribute(attn_mma, cudaFuncAttributeMaxDynamicSharedMemorySize, ATTN_SMEM);
    (void)cudaFuncSetAttribute(gemm_mma<0>, cudaFuncAttributeMaxDynamicSharedMemorySize, GEMM_SMEM);
    (void)cudaFuncSetAttribute(gemm_mma<1>, cudaFuncAttributeMaxDynamicSharedMemorySize, GEMM_SMEM);
    (void)cudaFuncSetAttribute(gemm_mma<2>, cudaFuncAttributeMaxDynamicSharedMemorySize, GEMM_SMEM);

    cvt16<0><<<(MROWS * 512 + 255) / 256, 256>>>(q,   MROWS * 512);
    cvt16<1><<<(MROWS * 512 + 255) / 256, 256>>>(kv,  MROWS * 512);
    cvt16<2><<<(1024 * 512 + 255) / 256, 256>>>(Wq,  1024 * 512);
    cvt16<3><<<(2048 * 512 + 255) / 256, 256>>>(Wkv, 2048 * 512);
    cvt16<4><<<(1024 * 512 + 255) / 256, 256>>>(W0,  1024 * 512);

    gemm_mma<0><<<dim3(EDIM / 128, MROWS / 128), 256, GEMM_SMEM>>>(nullptr);
    gemm_mma<1><<<dim3(2 * EDIM / 128, MROWS / 128), 256, GEMM_SMEM>>>(nullptr);
    attn_mma<<<dim3(SEQ / 128, BATCH * HEADS), 256, ATTN_SMEM>>>();
    gemm_mma<2><<<dim3(DMODEL / 128, MROWS / 128), 256, GEMM_SMEM>>>(out);
}

// round 16
// speedup vs baseline: 3.2726x; 1.3697x over previous
#include <cuda_runtime.h>
#include <cuda_bf16.h>
#include <cuda_fp16.h>
#include <cstdint>

// Problem constants
#define BATCH   4
#define SEQ     2048
#define DMODEL  1024
#define HEADS   16
#define DHEAD   64
#define EDIM    1024
#define MROWS   (BATCH * SEQ)     // 8192
#define KDIM    1024
#define QSCALE  (0.125f * 1.44269504088896340736f)   // 1/sqrt(64) * log2(e)

// ---------------------------------------------------------------------------
// Scratch (device globals; no allocation allowed)
// ---------------------------------------------------------------------------
__device__ __align__(256) __half g_Q [(size_t)BATCH * HEADS * SEQ * DHEAD];
__device__ __align__(256) __half g_K [(size_t)BATCH * HEADS * SEQ * DHEAD];
__device__ __align__(256) __half g_V [(size_t)BATCH * HEADS * SEQ * DHEAD];
__device__ __align__(256) __half g_Xq [(size_t)MROWS * KDIM];
__device__ __align__(256) __half g_Xkv[(size_t)MROWS * KDIM];
__device__ __align__(256) __half g_O  [(size_t)MROWS * KDIM];
__device__ __align__(256) __half g_Wq16 [(size_t)1024 * KDIM];
__device__ __align__(256) __half g_Wkv16[(size_t)2048 * KDIM];
__device__ __align__(256) __half g_W016 [(size_t)1024 * KDIM];

// ---------------------------------------------------------------------------
// Helpers
// ---------------------------------------------------------------------------
__device__ __forceinline__ uint32_t smem_u32(const void* p) {
    uint32_t a;
    asm("{ .reg .u64 t; cvta.to.shared.u64 t, %1; cvt.u32.u64 %0, t; }" : "=r"(a) : "l"(p));
    return a;
}
__device__ __forceinline__ void cp_async16(uint32_t smem_addr, const void* gptr) {
    asm volatile("cp.async.cg.shared.global [%0], [%1], 16;" :: "r"(smem_addr), "l"(gptr));
}
#define CP_COMMIT() asm volatile("cp.async.commit_group;" ::: "memory")
#define CP_WAIT(n)  asm volatile("cp.async.wait_group %0;" :: "n"(n) : "memory")

__device__ __forceinline__ void ldmatrix_x4(uint32_t& r0, uint32_t& r1, uint32_t& r2,
                                            uint32_t& r3, uint32_t addr) {
    asm volatile("ldmatrix.sync.aligned.m8n8.x4.shared.b16 {%0,%1,%2,%3}, [%4];"
                 : "=r"(r0), "=r"(r1), "=r"(r2), "=r"(r3) : "r"(addr));
}
__device__ __forceinline__ void ldmatrix_x4_trans(uint32_t& r0, uint32_t& r1, uint32_t& r2,
                                                  uint32_t& r3, uint32_t addr) {
    asm volatile("ldmatrix.sync.aligned.m8n8.x4.trans.shared.b16 {%0,%1,%2,%3}, [%4];"
                 : "=r"(r0), "=r"(r1), "=r"(r2), "=r"(r3) : "r"(addr));
}
__device__ __forceinline__ void mma_f16(float* c,
                                        uint32_t a0, uint32_t a1, uint32_t a2, uint32_t a3,
                                        uint32_t b0, uint32_t b1) {
    asm volatile(
        "mma.sync.aligned.m16n8k16.row.col.f32.f16.f16.f32 "
        "{%0,%1,%2,%3}, {%4,%5,%6,%7}, {%8,%9}, {%0,%1,%2,%3};"
        : "+f"(c[0]), "+f"(c[1]), "+f"(c[2]), "+f"(c[3])
        : "r"(a0), "r"(a1), "r"(a2), "r"(a3), "r"(b0), "r"(b1));
}
__device__ __forceinline__ uint32_t pack_h2(float x, float y) {
    __half2 t = __halves2half2(__float2half(x), __float2half(y));
    return *reinterpret_cast<uint32_t*>(&t);
}
__device__ __forceinline__ uint32_t ex2_f16x2(uint32_t x) {
    uint32_t r;
    asm volatile("ex2.approx.f16x2 %0, %1;" : "=r"(r) : "r"(x));
    return r;
}

// ---------------------------------------------------------------------------
// Merged conversion: one launch converts all five fp32 tensors to fp16.
// Ranges (in float2 units): q 4M | kv 4M | Wq 0.5M | Wkv 1M | W0 0.5M
// ---------------------------------------------------------------------------
#define R_Q   (MROWS * 512)                 // 4194304
#define R_KV  (R_Q + MROWS * 512)           // 8388608
#define R_WQ  (R_KV + 1024 * 512)           // 8912896
#define R_WKV (R_WQ + 2048 * 512)           // 9961472
#define R_W0  (R_WKV + 1024 * 512)          // 10485760

__global__ void cvt_all(const float* __restrict__ q, const float* __restrict__ kv,
                        const float* __restrict__ Wq, const float* __restrict__ Wkv,
                        const float* __restrict__ W0) {
    int idx = blockIdx.x * blockDim.x + threadIdx.x;
    if (idx >= R_W0) return;
    const float* src;
    __half* dst;
    int off;
    if (idx < R_Q)        { src = q;   dst = g_Xq;    off = idx; }
    else if (idx < R_KV)  { src = kv;  dst = g_Xkv;   off = idx - R_Q; }
    else if (idx < R_WQ)  { src = Wq;  dst = g_Wq16;  off = idx - R_KV; }
    else if (idx < R_WKV) { src = Wkv; dst = g_Wkv16; off = idx - R_WQ; }
    else                  { src = W0;  dst = g_W016;  off = idx - R_WKV; }
    float2 v = *reinterpret_cast<const float2*>(src + (size_t)off * 2);
    *reinterpret_cast<__half2*>(dst + (size_t)off * 2) =
        __halves2half2(__float2half(v.x), __float2half(v.y));
}

// ---------------------------------------------------------------------------
// fp16 single-product TN GEMM: C = A . W^T, K=1024, tile 128x128, BK=64.
// MODE 0/1 epilogues stage the tile in smem for coalesced vector stores.
// ---------------------------------------------------------------------------
#define GNCH        (KDIM / 64)          // 16
#define ROWB        144
#define TILE_B      (128 * ROWB)         // 18432
#define STAGE_B     (2 * TILE_B)         // 36864
#define GEMM_SMEM   (3 * STAGE_B)        // 110592
#define EROWH       136                  // epilogue stage row: 128 halves + pad
#define EROWB       (EROWH * 2)          // 272 bytes

template <int MODE>
__global__ __launch_bounds__(256) void gemm_mma(float* __restrict__ C) {
    extern __shared__ char smem[];
    const uint32_t sb = smem_u32(smem);
    const int tid = threadIdx.x, wid = tid >> 5, lane = tid & 31;
    const int wm = wid >> 2, wn = wid & 3;
    const int m0 = blockIdx.y * 128, n0 = blockIdx.x * 128;

    const __half* Ag = (MODE == 0) ? g_Xq : (MODE == 1) ? g_Xkv : g_O;
    const __half* Wg = (MODE == 0) ? g_Wq16 : (MODE == 1) ? g_Wkv16 : g_W016;
    Ag += (size_t)m0 * KDIM;
    Wg += (size_t)n0 * KDIM;

    float acc[4][4][4];
#pragma unroll
    for (int i = 0; i < 4; i++)
#pragma unroll
        for (int j = 0; j < 4; j++)
#pragma unroll
            for (int e = 0; e < 4; e++) acc[i][j][e] = 0.0f;

    auto load_stage = [&](int ch, int s) {
        uint32_t base = sb + s * STAGE_B;
#pragma unroll
        for (int t = 0; t < 8; t++) {
            int idx = tid + t * 256;
            int op  = idx >> 10;
            int row = (idx >> 3) & 127;
            int ck  = idx & 7;
            const __half* src = op ? Wg : Ag;
            cp_async16(base + op * TILE_B + row * ROWB + ck * 16,
                       src + (size_t)row * KDIM + ch * 64 + ck * 8);
        }
        CP_COMMIT();
    };

    load_stage(0, 0);
    load_stage(1, 1);

    const uint32_t a_row = (uint32_t)(wm * 64 + (lane & 15));
    const uint32_t a_kb  = (uint32_t)(((lane >> 4) & 1) * 16);
    const uint32_t b_row = (uint32_t)(wn * 32 + (lane & 7) + ((lane >> 4) & 1) * 8);
    const uint32_t b_kb  = (uint32_t)(((lane >> 3) & 1) * 16);

    for (int ch = 0; ch < GNCH; ch++) {
        if (ch + 1 < GNCH) { CP_WAIT(1); } else { CP_WAIT(0); }
        __syncthreads();
        if (ch + 2 < GNCH) load_stage(ch + 2, (ch + 2) % 3);

        uint32_t aBase = sb + (ch % 3) * STAGE_B;
        uint32_t wBase = aBase + TILE_B;
#pragma unroll
        for (int ks = 0; ks < 4; ks++) {
            uint32_t a[4][4], b[4][2];
#pragma unroll
            for (int i = 0; i < 4; i++) {
                uint32_t off = (a_row + i * 16) * ROWB + ks * 32 + a_kb;
                ldmatrix_x4(a[i][0], a[i][1], a[i][2], a[i][3], aBase + off);
            }
#pragma unroll
            for (int j2 = 0; j2 < 2; j2++) {
                uint32_t r0, r1, r2, r3;
                uint32_t addr = wBase + (b_row + j2 * 16) * ROWB + ks * 32 + b_kb;
                ldmatrix_x4(r0, r1, r2, r3, addr);
                b[j2 * 2][0] = r0; b[j2 * 2][1] = r1;
                b[j2 * 2 + 1][0] = r2; b[j2 * 2 + 1][1] = r3;
            }
#pragma unroll
            for (int i = 0; i < 4; i++)
#pragma unroll
                for (int j = 0; j < 4; j++)
                    mma_f16(acc[i][j], a[i][0], a[i][1], a[i][2], a[i][3],
                            b[j][0], b[j][1]);
        }
    }

    const int g = lane >> 2, tq = lane & 3;

    if (MODE == 2) {
#pragma unroll
        for (int i = 0; i < 4; i++)
#pragma unroll
            for (int e = 0; e < 2; e++) {
                int m = m0 + wm * 64 + i * 16 + g + e * 8;
#pragma unroll
                for (int j = 0; j < 4; j++)
#pragma unroll
                    for (int x = 0; x < 2; x++) {
                        int n = n0 + wn * 32 + j * 8 + tq * 2 + x;
                        C[(size_t)m * 1024 + n] = acc[i][j][e * 2 + x];
                    }
            }
        return;
    }

    // ---- Staged epilogue for MODE 0/1: permute into smem, vector-store out.
    __syncthreads();   // all reads of stage smem are complete
    __half* ep = reinterpret_cast<__half*>(smem);
#pragma unroll
    for (int i = 0; i < 4; i++) {
#pragma unroll
        for (int e = 0; e < 2; e++) {
            int ml = wm * 64 + i * 16 + g + e * 8;       // local row 0..127
#pragma unroll
            for (int j = 0; j < 4; j++) {
#pragma unroll
                for (int x = 0; x < 2; x++) {
                    int n = wn * 32 + j * 8 + tq * 2 + x; // local col 0..127
                    float v = acc[i][j][e * 2 + x];
                    int col;
                    if (MODE == 0) {
                        // n = d*16+h (within tile: dl = n>>4, h = n&15)
                        col = (n & 15) * 8 + (n >> 4);
                        v *= QSCALE;
                    } else {
                        // n = d*32 + kk*16 + h
                        col = ((n >> 4) & 1) * 64 + (n & 15) * 4 + (n >> 5);
                    }
                    ep[ml * EROWH + col] = __float2half(v);
                }
            }
        }
    }
    __syncthreads();

    if (MODE == 0) {
        // (m, h) pairs -> 16B stores of 8 d-contiguous halves
        const int d0 = n0 >> 4;
#pragma unroll
        for (int it = 0; it < 8; it++) {
            int pair = tid + it * 256;        // 0..2047
            int ml = pair & 127;
            int h  = pair >> 7;               // 0..15
            int m  = m0 + ml;
            int b  = m >> 11, t = m & 2047;
            uint4 val = *reinterpret_cast<uint4*>(ep + ml * EROWH + h * 8);
            size_t a5 = ((((size_t)b * HEADS + h) * SEQ + t) << 6) + d0;
            *reinterpret_cast<uint4*>(&g_Q[a5]) = val;
        }
    } else {
        // (m, kk, h) triples -> 8B stores of 4 d-contiguous halves
        const int d0 = n0 >> 5;
#pragma unroll
        for (int it = 0; it < 16; it++) {
            int trip = tid + it * 256;        // 0..4095
            int ml  = trip & 127;
            int sel = trip >> 7;              // 0..31: kk*16 + h
            int kk  = sel >> 4, h = sel & 15;
            int m   = m0 + ml;
            int b   = m >> 11, t = m & 2047;
            uint2 val = *reinterpret_cast<uint2*>(ep + ml * EROWH + kk * 64 + h * 4);
            size_t a5 = ((((size_t)b * HEADS + h) * SEQ + t) << 6) + d0;
            __half* dst = kk ? g_V : g_K;
            *reinterpret_cast<uint2*>(&dst[a5]) = val;
        }
    }
}

// ---------------------------------------------------------------------------
// Flash attention (unchanged from round 15): fp16 single-product QK,
// log2-domain softmax with ex2.approx.f16x2, single-product PV.
// ---------------------------------------------------------------------------
#define AROWB    144
#define ATILE_B  (64 * AROWB)            // 9216
#define ASTAGE_B (2 * ATILE_B)           // 18432  (K | V)
#define ATTN_SMEM (3 * ASTAGE_B)         // 55296

__global__ __launch_bounds__(256) void attn_mma() {
    extern __shared__ char smem[];
    const uint32_t sb = smem_u32(smem);
    const int tid = threadIdx.x, wid = tid >> 5, lane = tid & 31;
    const int g = lane >> 2, tq = lane & 3;
    const int bh = blockIdx.y;
    const int t0 = blockIdx.x << 7;

    const size_t bhoff = (size_t)bh * SEQ * DHEAD;
    const __half* Qg = g_Q + bhoff + (size_t)t0 * DHEAD;
    const __half* Kg = g_K + bhoff;
    const __half* Vg = g_V + bhoff;

#pragma unroll
    for (int t = 0; t < 4; t++) {
        int idx = tid + t * 256;
        int r   = idx >> 3;
        int ck  = idx & 7;
        cp_async16(sb + r * AROWB + ck * 16, Qg + (size_t)r * DHEAD + ck * 8);
    }
    CP_COMMIT();
    CP_WAIT(0);
    __syncthreads();

    uint32_t qf[4][4];
    {
        uint32_t qrow = (uint32_t)(wid * 16 + (lane & 15));
        uint32_t kb   = (uint32_t)(((lane >> 4) & 1) * 16);
#pragma unroll
        for (int ks = 0; ks < 4; ks++) {
            uint32_t addr = sb + qrow * AROWB + ks * 32 + kb;
            ldmatrix_x4(qf[ks][0], qf[ks][1], qf[ks][2], qf[ks][3], addr);
        }
    }
    __syncthreads();

    auto load_kv = [&](int jt, int s) {
        uint32_t base = sb + s * ASTAGE_B;
#pragma unroll
        for (int t = 0; t < 4; t++) {
            int idx = tid + t * 256;
            int mat = idx >> 9;
            int r   = (idx >> 3) & 63;
            int ck  = idx & 7;
            const __half* src = mat ? Vg : Kg;
            cp_async16(base + mat * ATILE_B + r * AROWB + ck * 16,
                       src + (size_t)(jt * 64 + r) * DHEAD + ck * 8);
        }
        CP_COMMIT();
    };

    load_kv(0, 0);
    load_kv(1, 1);

    float oacc[8][4];
#pragma unroll
    for (int j = 0; j < 8; j++)
#pragma unroll
        for (int e = 0; e < 4; e++) oacc[j][e] = 0.0f;
    float mr0 = -1e30f, mr1 = -1e30f, lr0 = 0.0f, lr1 = 0.0f;

    const uint32_t kb_row = (uint32_t)((lane & 7) + ((lane >> 4) & 1) * 8);
    const uint32_t kb_kb  = (uint32_t)(((lane >> 3) & 1) * 16);
    const uint32_t v_row  = (uint32_t)((lane & 7) + ((lane >> 3) & 1) * 8);
    const uint32_t v_cb   = (uint32_t)(((lane >> 4) & 1) * 8 * 2);

    for (int jt = 0; jt < SEQ / 64; jt++) {
        if (jt + 1 < SEQ / 64) { CP_WAIT(1); } else { CP_WAIT(0); }
        __syncthreads();
        if (jt + 2 < SEQ / 64) load_kv(jt + 2, (jt + 2) % 3);
        uint32_t st = sb + (jt % 3) * ASTAGE_B;

        float sacc[8][4];
#pragma unroll
        for (int j = 0; j < 8; j++)
#pragma unroll
            for (int e = 0; e < 4; e++) sacc[j][e] = 0.0f;
#pragma unroll
        for (int ks = 0; ks < 4; ks++) {
            uint32_t bt[8][2];
#pragma unroll
            for (int j2 = 0; j2 < 4; j2++) {
                uint32_t r0, r1, r2, r3;
                uint32_t addr = st + (kb_row + j2 * 16) * AROWB + ks * 32 + kb_kb;
                ldmatrix_x4(r0, r1, r2, r3, addr);
                bt[j2 * 2][0] = r0; bt[j2 * 2][1] = r1;
                bt[j2 * 2 + 1][0] = r2; bt[j2 * 2 + 1][1] = r3;
            }
#pragma unroll
            for (int j = 0; j < 8; j++)
                mma_f16(sacc[j], qf[ks][0], qf[ks][1], qf[ks][2], qf[ks][3],
                        bt[j][0], bt[j][1]);
        }

        float mx0 = -1e30f, mx1 = -1e30f;
#pragma unroll
        for (int j = 0; j < 8; j++) {
            mx0 = fmaxf(mx0, fmaxf(sacc[j][0], sacc[j][1]));
            mx1 = fmaxf(mx1, fmaxf(sacc[j][2], sacc[j][3]));
        }
        mx0 = fmaxf(mx0, __shfl_xor_sync(0xffffffffu, mx0, 1));
        mx0 = fmaxf(mx0, __shfl_xor_sync(0xffffffffu, mx0, 2));
        mx1 = fmaxf(mx1, __shfl_xor_sync(0xffffffffu, mx1, 1));
        mx1 = fmaxf(mx1, __shfl_xor_sync(0xffffffffu, mx1, 2));
        float mn0 = fmaxf(mr0, mx0), mn1 = fmaxf(mr1, mx1);
        float al0 = exp2f(mr0 - mn0), al1 = exp2f(mr1 - mn1);
        mr0 = mn0; mr1 = mn1;

        uint32_t pfr[8][2];
        float sum0 = 0.0f, sum1 = 0.0f;
#pragma unroll
        for (int j = 0; j < 8; j++) {
            pfr[j][0] = ex2_f16x2(pack_h2(sacc[j][0] - mn0, sacc[j][1] - mn0));
            pfr[j][1] = ex2_f16x2(pack_h2(sacc[j][2] - mn1, sacc[j][3] - mn1));
            float2 f0 = __half22float2(*reinterpret_cast<__half2*>(&pfr[j][0]));
            float2 f1 = __half22float2(*reinterpret_cast<__half2*>(&pfr[j][1]));
            sum0 += f0.x + f0.y;
            sum1 += f1.x + f1.y;
        }
        sum0 += __shfl_xor_sync(0xffffffffu, sum0, 1);
        sum0 += __shfl_xor_sync(0xffffffffu, sum0, 2);
        sum1 += __shfl_xor_sync(0xffffffffu, sum1, 1);
        sum1 += __shfl_xor_sync(0xffffffffu, sum1, 2);
        lr0 = lr0 * al0 + sum0;
        lr1 = lr1 * al1 + sum1;
#pragma unroll
        for (int j = 0; j < 8; j++) {
            oacc[j][0] *= al0; oacc[j][1] *= al0;
            oacc[j][2] *= al1; oacc[j][3] *= al1;
        }

#pragma unroll
        for (int cs = 0; cs < 4; cs++) {
            int j0 = cs * 2, j1 = cs * 2 + 1;
            uint32_t vt[8][2];
#pragma unroll
            for (int jd2 = 0; jd2 < 4; jd2++) {
                uint32_t r0, r1, r2, r3;
                uint32_t addr = st + ATILE_B + (cs * 16 + v_row) * AROWB
                              + jd2 * 32 + v_cb;
                ldmatrix_x4_trans(r0, r1, r2, r3, addr);
                vt[jd2 * 2][0] = r0; vt[jd2 * 2][1] = r1;
                vt[jd2 * 2 + 1][0] = r2; vt[jd2 * 2 + 1][1] = r3;
            }
#pragma unroll
            for (int jd = 0; jd < 8; jd++)
                mma_f16(oacc[jd], pfr[j0][0], pfr[j0][1], pfr[j1][0], pfr[j1][1],
                        vt[jd][0], vt[jd][1]);
        }
    }

    const int bq = bh >> 4;
    const int h  = bh & 15;
    float inv0 = 1.0f / lr0, inv1 = 1.0f / lr1;
#pragma unroll
    for (int e = 0; e < 2; e++) {
        int trow = t0 + wid * 16 + g + e * 8;
        float inv = e ? inv1 : inv0;
        size_t rowbase = (size_t)(bq * SEQ + trow) * KDIM + h * DHEAD;
#pragma unroll
        for (int jd = 0; jd < 8; jd++) {
            int d = jd * 8 + tq * 2;
            float v0 = oacc[jd][e * 2 + 0] * inv;
            float v1 = oacc[jd][e * 2 + 1] * inv;
            *reinterpret_cast<__half2*>(g_O + rowbase + d) =
                __halves2half2(__float2half(v0), __float2half(v1));
        }
    }
}

// ---------------------------------------------------------------------------
extern "C" void kernel_launch(void* const* d_in, const int* in_sizes, int n_in,
                              void* d_out, int out_size) {
    const float* q   = (const float*)d_in[0];
    const float* kv  = (const float*)d_in[1];
    const float* Wq  = (const float*)d_in[2];
    const float* Wkv = (const float*)d_in[3];
    const float* W0  = (const float*)d_in[4];
    float* out = (float*)d_out;
    (void)in_sizes; (void)n_in; (void)out_size;

    (void)cudaFuncSetAttribute(attn_mma, cudaFuncAttributeMaxDynamicSharedMemorySize, ATTN_SMEM);
    (void)cudaFuncSetAttribute(gemm_mma<0>, cudaFuncAttributeMaxDynamicSharedMemorySize, GEMM_SMEM);
    (void)cudaFuncSetAttribute(gemm_mma<1>, cudaFuncAttributeMaxDynamicSharedMemorySize, GEMM_SMEM);
    (void)cudaFuncSetAttribute(gemm_mma<2>, cudaFuncAttributeMaxDynamicSharedMemorySize, GEMM_SMEM);

    cvt_all<<<(R_W0 + 255) / 256, 256>>>(q, kv, Wq, Wkv, W0);

    gemm_mma<0><<<dim3(EDIM / 128, MROWS / 128), 256, GEMM_SMEM>>>(nullptr);
    gemm_mma<1><<<dim3(2 * EDIM / 128, MROWS / 128), 256, GEMM_SMEM>>>(nullptr);
    attn_mma<<<dim3(SEQ / 128, BATCH * HEADS), 256, ATTN_SMEM>>>();
    gemm_mma<2><<<dim3(DMODEL / 128, MROWS / 128), 256, GEMM_SMEM>>>(out);
}